// round 9
// baseline (speedup 1.0000x reference)
#include <cuda_runtime.h>
#include <cuda_bf16.h>
#include <math_constants.h>
#include <cstdint>

// ---------------------------------------------------------------------------
// MiTA Attention. compute_103 PTX target (no tcgen05) -> mma.sync HMMA bf16.
// q/k via bf16x6 split (err ~1e-7, decision-safe); v & proj via bf16x3.
// ---------------------------------------------------------------------------

#define BATCH 8
#define NTOK 1025
#define CDIM 1024
#define HEADS 16
#define HDIM 64
#define MEXP 25
#define KSEL 25
#define GRID 32
#define POOLN 5
#define SCALE 0.125f
#define MROWS (BATCH * NTOK)       // 8200
#define BH (BATCH * HEADS)         // 128
#define K6 (6 * CDIM)              // 6144
#define KT3 (3 * CDIM)             // 3072

// ---------------- scratch ----------------
__device__ float g_qkv[BATCH * NTOK * 3 * CDIM];
__device__ float g_router[BATCH * MEXP * CDIM];
__device__ float g_rlog[BH * MEXP * NTOK];
__device__ float g_gate[BH * MEXP * NTOK];        // layout [bh][m][n]
__device__ int   g_topk[BH * MEXP * KSEL];
__device__ float g_agentv[BH * MEXP * HDIM];
__device__ float g_avpart[4][BH * MEXP * HDIM];
__device__ float g_attn[BATCH * NTOK * CDIM];
__device__ __nv_bfloat16 g_a6[MROWS * K6];        // A'6 for GEMM1a
__device__ __nv_bfloat16 g_a3[MROWS * KT3];       // A'3 for GEMM1b / GEMM2
__device__ __nv_bfloat16 g_b6qk[2 * CDIM * K6];
__device__ __nv_bfloat16 g_b3v[CDIM * KT3];
__device__ __nv_bfloat16 g_b3p[CDIM * KT3];

// ======================= helpers ===========================================
__device__ __forceinline__ uint32_t smem_u32(const void* p) {
    uint32_t a;
    asm("{ .reg .u64 t; cvta.to.shared.u64 t, %1; cvt.u32.u64 %0, t; }" : "=r"(a) : "l"(p));
    return a;
}
#define CP16(dst, src, nbytes) \
    asm volatile("cp.async.cg.shared.global [%0], [%1], 16, %2;" \
        :: "r"(dst), "l"(src), "r"(nbytes) : "memory")

__device__ __forceinline__ void ldmx4(uint32_t& r0, uint32_t& r1, uint32_t& r2,
                                      uint32_t& r3, uint32_t addr) {
    asm volatile("ldmatrix.sync.aligned.m8n8.x4.shared.b16 {%0,%1,%2,%3}, [%4];"
        : "=r"(r0), "=r"(r1), "=r"(r2), "=r"(r3) : "r"(addr));
}
__device__ __forceinline__ void mma16816(float* c, const uint32_t* a,
                                         uint32_t b0, uint32_t b1) {
    asm volatile(
        "mma.sync.aligned.m16n8k16.row.col.f32.bf16.bf16.f32 "
        "{%0,%1,%2,%3}, {%4,%5,%6,%7}, {%8,%9}, {%0,%1,%2,%3};"
        : "+f"(c[0]), "+f"(c[1]), "+f"(c[2]), "+f"(c[3])
        : "r"(a[0]), "r"(a[1]), "r"(a[2]), "r"(a[3]), "r"(b0), "r"(b1));
}

// ======================= HMMA GEMM =========================================
#define BM 128
#define BN 128
#define BKE 64
#define STAGES 3
#define TILE_BYTES (128 * 128)
#define SM_A 0
#define SM_B (STAGES * TILE_BYTES)
#define DYN_SMEM (2 * STAGES * TILE_BYTES + 1024)

__device__ __forceinline__ void load_tile(
    const __nv_bfloat16* __restrict__ A, int lda,
    const __nv_bfloat16* __restrict__ Bt, int ldb,
    int Mrows, int rowBase, int colBase, int kt, int buf, uint32_t sb, int tid)
{
    const int k0 = kt * BKE;
    #pragma unroll
    for (int j = 0; j < 4; j++) {
        int i = tid + 256 * j;
        int r = i >> 3, c = i & 7;
        uint32_t dst = sb + SM_A + buf * TILE_BYTES
                     + r * 128 + ((c * 16) ^ ((r & 7) * 16));
        bool ok = (rowBase + r) < Mrows;
        const __nv_bfloat16* src = ok ? (A + (size_t)(rowBase + r) * lda + k0 + c * 8) : A;
        CP16(dst, src, ok ? 16 : 0);
    }
    #pragma unroll
    for (int j = 0; j < 4; j++) {
        int i = tid + 256 * j;
        int r = i >> 3, c = i & 7;
        uint32_t dst = sb + SM_B + buf * TILE_BYTES
                     + r * 128 + ((c * 16) ^ ((r & 7) * 16));
        const __nv_bfloat16* src = Bt + (size_t)(colBase + r) * ldb + k0 + c * 8;
        CP16(dst, src, 16);
    }
    asm volatile("cp.async.commit_group;" ::: "memory");
}

__global__ __launch_bounds__(256, 2) void tc_gemm(
    const __nv_bfloat16* __restrict__ A, int lda,
    const __nv_bfloat16* __restrict__ Bt, int ldb,
    const float* __restrict__ bias, float* __restrict__ C, int ldc,
    int Mrows, int nkt)
{
    extern __shared__ char dsm[];
    uint32_t sb = (smem_u32(dsm) + 1023u) & ~1023u;
    const int tid  = threadIdx.x;
    const int lane = tid & 31, w = tid >> 5;
    const int wm = w >> 1, wn = w & 1;
    const int rowBase = blockIdx.y * BM;
    const int colBase = blockIdx.x * BN;

    const uint32_t xm = (lane & 7) * 16;
    uint32_t aRow[2];
    #pragma unroll
    for (int mi = 0; mi < 2; mi++)
        aRow[mi] = (uint32_t)(wm * 32 + mi * 16 + (lane & 15)) * 128u;
    const uint32_t aCol = 16u * (lane >> 4);
    uint32_t bRow[4];
    #pragma unroll
    for (int p = 0; p < 4; p++)
        bRow[p] = (uint32_t)(wn * 64 + p * 16 + (lane & 7) + 8 * (lane >> 4)) * 128u;
    const uint32_t bCol = 16u * ((lane >> 3) & 1);

    float acc[2][8][4];
    #pragma unroll
    for (int mi = 0; mi < 2; mi++)
        #pragma unroll
        for (int ni = 0; ni < 8; ni++)
            #pragma unroll
            for (int r = 0; r < 4; r++) acc[mi][ni][r] = 0.f;

    #pragma unroll
    for (int s = 0; s < STAGES; s++)
        load_tile(A, lda, Bt, ldb, Mrows, rowBase, colBase, s, s, sb, tid);

    for (int kt = 0; kt < nkt; kt++) {
        const int buf = kt % STAGES;
        const int remain = nkt - 1 - kt;
        if (remain >= 2)      asm volatile("cp.async.wait_group 2;" ::: "memory");
        else if (remain == 1) asm volatile("cp.async.wait_group 1;" ::: "memory");
        else                  asm volatile("cp.async.wait_group 0;" ::: "memory");
        __syncthreads();

        const uint32_t baseA = sb + SM_A + buf * TILE_BYTES;
        const uint32_t baseB = sb + SM_B + buf * TILE_BYTES;
        #pragma unroll
        for (int kf = 0; kf < 4; kf++) {
            const uint32_t kb = kf * 32;
            uint32_t af[2][4], bf[8][2];
            #pragma unroll
            for (int mi = 0; mi < 2; mi++)
                ldmx4(af[mi][0], af[mi][1], af[mi][2], af[mi][3],
                      baseA + aRow[mi] + ((kb + aCol) ^ xm));
            #pragma unroll
            for (int p = 0; p < 4; p++)
                ldmx4(bf[2 * p][0], bf[2 * p][1], bf[2 * p + 1][0], bf[2 * p + 1][1],
                      baseB + bRow[p] + ((kb + bCol) ^ xm));
            #pragma unroll
            for (int mi = 0; mi < 2; mi++)
                #pragma unroll
                for (int ni = 0; ni < 8; ni++)
                    mma16816(acc[mi][ni], af[mi], bf[ni][0], bf[ni][1]);
        }
        __syncthreads();
        if (kt + STAGES < nkt)
            load_tile(A, lda, Bt, ldb, Mrows, rowBase, colBase, kt + STAGES, buf, sb, tid);
    }

    const int colW = colBase + wn * 64 + 2 * (lane & 3);
    #pragma unroll
    for (int mi = 0; mi < 2; mi++) {
        int r0 = rowBase + wm * 32 + mi * 16 + (lane >> 2);
        #pragma unroll
        for (int ni = 0; ni < 8; ni++) {
            int col = colW + ni * 8;
            float bx = 0.f, by = 0.f;
            if (bias) { bx = bias[col]; by = bias[col + 1]; }
            if (r0 < Mrows)
                *(float2*)&C[(size_t)r0 * ldc + col] =
                    make_float2(acc[mi][ni][0] + bx, acc[mi][ni][1] + by);
            if (r0 + 8 < Mrows)
                *(float2*)&C[(size_t)(r0 + 8) * ldc + col] =
                    make_float2(acc[mi][ni][2] + bx, acc[mi][ni][3] + by);
        }
    }
}

// ======================= split / transpose conversions =====================
// Fused: one read of src -> A'6 = [Ah|Ah|Al|Ah|Am|Am] AND A'3 = [Ah|Ah|Am]
__global__ __launch_bounds__(256) void split63_rows(
    const float* __restrict__ src, __nv_bfloat16* __restrict__ d6,
    __nv_bfloat16* __restrict__ d3, int total)
{
    int idx = blockIdx.x * 256 + threadIdx.x;
    if (idx >= total) return;
    int r = idx >> 10, k = idx & 1023;
    float v = src[idx];
    __nv_bfloat16 h = __float2bfloat16(v);
    float r1 = v - __bfloat162float(h);
    __nv_bfloat16 m = __float2bfloat16(r1);
    __nv_bfloat16 l = __float2bfloat16(r1 - __bfloat162float(m));
    size_t o6 = (size_t)r * K6 + k;
    d6[o6] = h;
    d6[o6 + 1024] = h;
    d6[o6 + 2048] = l;
    d6[o6 + 3072] = h;
    d6[o6 + 4096] = m;
    d6[o6 + 5120] = m;
    size_t o3 = (size_t)r * KT3 + k;
    d3[o3] = h;
    d3[o3 + 1024] = h;
    d3[o3 + 2048] = m;
}

// A'3 only (for GEMM2 input)
__global__ __launch_bounds__(256) void split3_rows(
    const float* __restrict__ src, __nv_bfloat16* __restrict__ dst, int total)
{
    int idx = blockIdx.x * 256 + threadIdx.x;
    if (idx >= total) return;
    int r = idx >> 10, k = idx & 1023;
    float v = src[idx];
    __nv_bfloat16 h = __float2bfloat16(v);
    __nv_bfloat16 m = __float2bfloat16(v - __bfloat162float(h));
    size_t o = (size_t)r * KT3 + k;
    dst[o] = h;
    dst[o + 1024] = h;
    dst[o + 2048] = m;
}

__global__ __launch_bounds__(256) void transpose_split6(
    const float* __restrict__ W, int ldw, __nv_bfloat16* __restrict__ Bt)
{
    __shared__ float t[32][33];
    int n0 = blockIdx.x * 32, k0 = blockIdx.y * 32;
    int tx = threadIdx.x & 31, ty = threadIdx.x >> 5;
    #pragma unroll
    for (int i = 0; i < 32; i += 8)
        t[ty + i][tx] = W[(size_t)(k0 + ty + i) * ldw + n0 + tx];
    __syncthreads();
    #pragma unroll
    for (int i = 0; i < 32; i += 8) {
        int n = n0 + ty + i, k = k0 + tx;
        float v = t[tx][ty + i];
        __nv_bfloat16 h = __float2bfloat16(v);
        float r1 = v - __bfloat162float(h);
        __nv_bfloat16 m = __float2bfloat16(r1);
        __nv_bfloat16 l = __float2bfloat16(r1 - __bfloat162float(m));
        size_t o = (size_t)n * K6 + k;
        Bt[o] = h;
        Bt[o + 1024] = m;
        Bt[o + 2048] = h;
        Bt[o + 3072] = l;
        Bt[o + 4096] = h;
        Bt[o + 5120] = m;
    }
}

__global__ __launch_bounds__(256) void transpose_split3(
    const float* __restrict__ W, int ldw, __nv_bfloat16* __restrict__ Bt)
{
    __shared__ float t[32][33];
    int n0 = blockIdx.x * 32, k0 = blockIdx.y * 32;
    int tx = threadIdx.x & 31, ty = threadIdx.x >> 5;
    #pragma unroll
    for (int i = 0; i < 32; i += 8)
        t[ty + i][tx] = W[(size_t)(k0 + ty + i) * ldw + n0 + tx];
    __syncthreads();
    #pragma unroll
    for (int i = 0; i < 32; i += 8) {
        int n = n0 + ty + i, k = k0 + tx;
        float v = t[tx][ty + i];
        __nv_bfloat16 h = __float2bfloat16(v);
        __nv_bfloat16 m = __float2bfloat16(v - __bfloat162float(h));
        size_t o = (size_t)n * KT3 + k;
        Bt[o] = h;
        Bt[o + 1024] = m;
        Bt[o + 2048] = h;
    }
}

// ======================= small pipeline kernels ============================
__global__ void router_pool_kernel()
{
    int blk = blockIdx.x;
    int b = blk / MEXP, m = blk % MEXP;
    int p = m / POOLN, q = m % POOLN;
    int hs = (p * GRID) / POOLN, he = ((p + 1) * GRID + POOLN - 1) / POOLN;
    int ws = (q * GRID) / POOLN, we = ((q + 1) * GRID + POOLN - 1) / POOLN;
    float inv = 1.0f / (float)((he - hs) * (we - ws));
    for (int c = threadIdx.x; c < CDIM; c += blockDim.x) {
        float s = 0.f;
        for (int h = hs; h < he; h++)
            for (int w = ws; w < we; w++)
                s += g_qkv[((size_t)(b * NTOK + h * GRID + w)) * (3 * CDIM) + c];
        g_router[(size_t)blk * CDIM + c] = s * inv;
    }
}

// logits: smem-staged, coalesced. Block = (64-token tile, bh), 256 threads.
// g_rlog[bh][m][n] = r_m . k_n ; g_gate[bh][m][n] = r_m . q_n
#define LT 64
__global__ __launch_bounds__(256) void logits_kernel()
{
    __shared__ float q_s[LT][65];
    __shared__ float k_s[LT][65];
    __shared__ float r_s[MEXP][65];

    int bh = blockIdx.y;
    int b = bh / HEADS, h = bh % HEADS;
    int n0 = blockIdx.x * LT;
    int tid = threadIdx.x;

    for (int i = tid; i < MEXP * 16; i += 256) {
        int m = i >> 4, c = (i & 15) * 4;
        float4 v = *(const float4*)&g_router[(size_t)(b * MEXP + m) * CDIM + h * HDIM + c];
        r_s[m][c] = v.x; r_s[m][c + 1] = v.y; r_s[m][c + 2] = v.z; r_s[m][c + 3] = v.w;
    }
    #pragma unroll
    for (int it = 0; it < 4; it++) {
        int i = tid + it * 256;
        int row = i >> 4, c = (i & 15) * 4;
        int n = n0 + row;
        float4 qv = make_float4(0.f, 0.f, 0.f, 0.f), kv = qv;
        if (n < NTOK) {
            const float* base = &g_qkv[(size_t)(b * NTOK + n) * (3 * CDIM) + h * HDIM + c];
            qv = *(const float4*)base;
            kv = *(const float4*)(base + CDIM);
        }
        q_s[row][c] = qv.x; q_s[row][c + 1] = qv.y; q_s[row][c + 2] = qv.z; q_s[row][c + 3] = qv.w;
        k_s[row][c] = kv.x; k_s[row][c + 1] = kv.y; k_s[row][c + 2] = kv.z; k_s[row][c + 3] = kv.w;
    }
    __syncthreads();

    const int nl = tid & 63;
    const int g = tid >> 6;                     // expert group: m = g + 4j
    float acck[7], accq[7];
    #pragma unroll
    for (int j = 0; j < 7; j++) { acck[j] = 0.f; accq[j] = 0.f; }

    for (int d = 0; d < HDIM; d++) {
        float qv = q_s[nl][d];
        float kv = k_s[nl][d];
        #pragma unroll
        for (int j = 0; j < 7; j++) {
            int m = g + 4 * j;
            int mc = (m < MEXP) ? m : 0;        // clamped; unused lanes never stored
            float r = r_s[mc][d];
            acck[j] += r * kv;
            accq[j] += r * qv;
        }
    }
    int n = n0 + nl;
    if (n < NTOK) {
        #pragma unroll
        for (int j = 0; j < 7; j++) {
            int m = g + 4 * j;
            if (m < MEXP) {
                size_t o = ((size_t)(bh * MEXP + m)) * NTOK + n;
                g_rlog[o] = acck[j];
                g_gate[o] = accq[j];
            }
        }
    }
}

__global__ __launch_bounds__(256) void softmax_topk_kernel()
{
    __shared__ float swv[8];
    __shared__ int   swi[8];
    __shared__ float selv[KSEL];
    __shared__ int   seli[KSEL];
    __shared__ float s_inv;

    int row = blockIdx.x;
    float* r = &g_rlog[(size_t)row * NTOK];
    int tid = threadIdx.x, lane = tid & 31, wid = tid >> 5;

    float vals[5];
    #pragma unroll
    for (int i = 0; i < 5; i++) {
        int n = tid + (i << 8);
        vals[i] = (n < NTOK) ? r[n] : -CUDART_INF_F;
    }

    for (int it = 0; it < KSEL; it++) {
        float bv = -CUDART_INF_F; int bi = 0x7FFFFFFF;
        #pragma unroll
        for (int i = 0; i < 5; i++) {
            int n = tid + (i << 8);
            float v = vals[i];
            if (v > bv || (v == bv && n < bi)) { bv = v; bi = n; }
        }
        #pragma unroll
        for (int off = 16; off > 0; off >>= 1) {
            float ov = __shfl_xor_sync(0xFFFFFFFFu, bv, off);
            int   oi = __shfl_xor_sync(0xFFFFFFFFu, bi, off);
            if (ov > bv || (ov == bv && oi < bi)) { bv = ov; bi = oi; }
        }
        if (lane == 0) { swv[wid] = bv; swi[wid] = bi; }
        __syncthreads();
        if (tid == 0) {
            float gv = swv[0]; int gi = swi[0];
            #pragma unroll
            for (int ww = 1; ww < 8; ww++)
                if (swv[ww] > gv || (swv[ww] == gv && swi[ww] < gi)) { gv = swv[ww]; gi = swi[ww]; }
            selv[it] = gv; seli[it] = gi;
        }
        __syncthreads();
        int sn = seli[it];
        if (tid == (sn & 255)) vals[sn >> 8] = -CUDART_INF_F;
    }

    if (tid < KSEL) g_topk[(size_t)row * KSEL + tid] = seli[tid];
    float mx = selv[0];
    for (int it = 0; it < KSEL; it++) {
        int sn = seli[it];
        if (tid == (sn & 255)) vals[sn >> 8] = selv[it];
    }

    float ev[5];
    float psum = 0.f;
    #pragma unroll
    for (int i = 0; i < 5; i++) {
        int n = tid + (i << 8);
        float e = (n < NTOK) ? __expf((vals[i] - mx) * SCALE) : 0.f;
        ev[i] = e;
        psum += e;
    }
    #pragma unroll
    for (int off = 16; off > 0; off >>= 1)
        psum += __shfl_xor_sync(0xFFFFFFFFu, psum, off);
    if (lane == 0) swv[wid] = psum;
    __syncthreads();
    if (tid == 0) {
        float s = 0.f;
        #pragma unroll
        for (int ww = 0; ww < 8; ww++) s += swv[ww];
        s_inv = 1.0f / s;
    }
    __syncthreads();
    float inv = s_inv;
    #pragma unroll
    for (int i = 0; i < 5; i++) {
        int n = tid + (i << 8);
        if (n < NTOK) r[n] = ev[i] * inv;
    }
}

// agent_value split 4 ways over tokens; deterministic two-phase reduce.
#define AV_TILES 33            // ceil(1025/32)
__global__ __launch_bounds__(256) void agent_value_part()
{
    __shared__ float p_s[MEXP][32];
    __shared__ float v_s[32][HDIM];
    int bh = blockIdx.x;
    int ch = blockIdx.y;
    int b = bh / HEADS, h = bh % HEADS;
    int tid = threadIdx.x;
    int tile0 = ch * 9;
    int tile1 = tile0 + 9; if (tile1 > AV_TILES) tile1 = AV_TILES;

    float acc[7];
    #pragma unroll
    for (int i = 0; i < 7; i++) acc[i] = 0.f;

    for (int tile = tile0; tile < tile1; tile++) {
        int t0 = tile * 32;
        for (int e = tid; e < MEXP * 32; e += 256) {
            int m = e / 32, n = e % 32;
            p_s[m][n] = (t0 + n < NTOK)
                ? g_rlog[((size_t)(bh * MEXP + m)) * NTOK + t0 + n] : 0.f;
        }
        for (int e = tid; e < 32 * HDIM; e += 256) {
            int n = e / HDIM, d = e % HDIM;
            v_s[n][d] = (t0 + n < NTOK)
                ? g_qkv[(size_t)(b * NTOK + t0 + n) * (3 * CDIM) + 2 * CDIM + h * HDIM + d]
                : 0.f;
        }
        __syncthreads();
        for (int n = 0; n < 32; n++) {
            #pragma unroll
            for (int i = 0; i < 7; i++) {
                int pidx = tid + 256 * i;
                if (pidx < MEXP * HDIM) {
                    int m = pidx >> 6, d = pidx & 63;
                    acc[i] += p_s[m][n] * v_s[n][d];
                }
            }
        }
        __syncthreads();
    }
    #pragma unroll
    for (int i = 0; i < 7; i++) {
        int pidx = tid + 256 * i;
        if (pidx < MEXP * HDIM)
            g_avpart[ch][(size_t)bh * MEXP * HDIM + pidx] = acc[i];
    }
}

__global__ __launch_bounds__(256) void agent_value_reduce()
{
    int idx = blockIdx.x * 256 + threadIdx.x;
    if (idx < BH * MEXP * HDIM)
        g_agentv[idx] = g_avpart[0][idx] + g_avpart[1][idx]
                      + g_avpart[2][idx] + g_avpart[3][idx];
}

#define TQ 16
__global__ __launch_bounds__(256) void attn_kernel()
{
    __shared__ float ag_s[MEXP][HDIM];
    __shared__ float q_s[TQ][HDIM];
    __shared__ float w_s[TQ][65];
    __shared__ int   sel_s[TQ][KSEL];

    int bh = blockIdx.y;
    int b = bh / HEADS, h = bh % HEADS;
    int n0 = blockIdx.x * TQ;
    int tid = threadIdx.x;

    for (int e = tid; e < MEXP * HDIM; e += 256)
        ((float*)ag_s)[e] = g_agentv[(size_t)bh * MEXP * HDIM + e];
    for (int e = tid; e < TQ * HDIM; e += 256) {
        int qi = e / HDIM, d = e % HDIM;
        int n = n0 + qi;
        q_s[qi][d] = (n < NTOK)
            ? g_qkv[(size_t)(b * NTOK + n) * (3 * CDIM) + h * HDIM + d] : 0.f;
    }
    __syncthreads();

    if (tid < TQ && n0 + tid < NTOK) {
        const float* gb = &g_gate[(size_t)bh * MEXP * NTOK + n0 + tid];   // [m][n] layout
        float best = -CUDART_INF_F; int ei = 0;
        #pragma unroll
        for (int m = 0; m < MEXP; m++) {
            float v = gb[(size_t)m * NTOK];
            w_s[tid][m] = v * SCALE;
            if (v > best) { best = v; ei = m; }
        }
        const int* tk = &g_topk[((size_t)(bh * MEXP + ei)) * KSEL];
        #pragma unroll
        for (int k = 0; k < KSEL; k++) sel_s[tid][k] = tk[k];
    }
    __syncthreads();

    int warp = tid >> 5, lane = tid & 31;
    for (int task = warp; task < TQ * KSEL; task += 8) {
        int qi = task / KSEL, k = task % KSEL;
        if (n0 + qi < NTOK) {
            int key = sel_s[qi][k];
            const float2* kp = (const float2*)
                &g_qkv[(size_t)(b * NTOK + key) * (3 * CDIM) + CDIM + h * HDIM];
            float2 kv = kp[lane];
            float2 qv = *(const float2*)&q_s[qi][2 * lane];
            float s = qv.x * kv.x + qv.y * kv.y;
            #pragma unroll
            for (int off = 16; off > 0; off >>= 1)
                s += __shfl_xor_sync(0xFFFFFFFFu, s, off);
            if (lane == 0) w_s[qi][MEXP + k] = s * SCALE;
        }
    }
    __syncthreads();

    if (tid < TQ && n0 + tid < NTOK) {
        float mx = -CUDART_INF_F;
        #pragma unroll
        for (int j = 0; j < MEXP + KSEL; j++) mx = fmaxf(mx, w_s[tid][j]);
        float sum = 0.f;
        #pragma unroll
        for (int j = 0; j < MEXP + KSEL; j++) {
            float e = __expf(w_s[tid][j] - mx);
            w_s[tid][j] = e;
            sum += e;
        }
        float inv = 1.0f / sum;
        #pragma unroll
        for (int j = 0; j < MEXP + KSEL; j++) w_s[tid][j] *= inv;
    }
    __syncthreads();

    int d = tid & 63;
    #pragma unroll
    for (int i = 0; i < 4; i++) {
        int qi = (tid >> 6) + i * 4;
        int n = n0 + qi;
        if (n < NTOK) {
            float o = 0.f;
            #pragma unroll
            for (int m = 0; m < MEXP; m++) o += w_s[qi][m] * ag_s[m][d];
            #pragma unroll
            for (int k = 0; k < KSEL; k++) {
                int key = sel_s[qi][k];
                o += w_s[qi][MEXP + k] *
                     g_qkv[(size_t)(b * NTOK + key) * (3 * CDIM) + 2 * CDIM + h * HDIM + d];
            }
            g_attn[(size_t)(b * NTOK + n) * CDIM + h * HDIM + d] = o;
        }
    }
}

// ---------------------------------------------------------------------------
extern "C" void kernel_launch(void* const* d_in, const int* in_sizes, int n_in,
                              void* d_out, int out_size)
{
    const float* x     = (const float*)d_in[0];
    const float* Wqkv  = (const float*)d_in[1];
    const float* Wproj = (const float*)d_in[2];
    const float* bproj = (const float*)d_in[3];
    float* out = (float*)d_out;

    float* qkv;   cudaGetSymbolAddress((void**)&qkv,   g_qkv);
    float* attn;  cudaGetSymbolAddress((void**)&attn,  g_attn);
    __nv_bfloat16* a6;   cudaGetSymbolAddress((void**)&a6,   g_a6);
    __nv_bfloat16* a3;   cudaGetSymbolAddress((void**)&a3,   g_a3);
    __nv_bfloat16* b6qk; cudaGetSymbolAddress((void**)&b6qk, g_b6qk);
    __nv_bfloat16* b3v;  cudaGetSymbolAddress((void**)&b3v,  g_b3v);
    __nv_bfloat16* b3p;  cudaGetSymbolAddress((void**)&b3p,  g_b3p);

    cudaFuncSetAttribute(tc_gemm, cudaFuncAttributeMaxDynamicSharedMemorySize, DYN_SMEM);

    // --- conversions for GEMM1 (A'6 + A'3 in one pass over x) ---
    split63_rows<<<(MROWS * CDIM + 255) / 256, 256>>>(x, a6, a3, MROWS * CDIM);
    {
        dim3 g(2 * CDIM / 32, CDIM / 32);
        transpose_split6<<<g, 256>>>(Wqkv, 3 * CDIM, b6qk);           // q,k columns
    }
    {
        dim3 g(CDIM / 32, CDIM / 32);
        transpose_split3<<<g, 256>>>(Wqkv + 2 * CDIM, 3 * CDIM, b3v); // v columns
    }
    // --- GEMM1a (q,k): bf16x6 ---
    {
        dim3 grid(2 * CDIM / BN, (MROWS + BM - 1) / BM);   // (16, 65)
        tc_gemm<<<grid, 256, DYN_SMEM>>>(a6, K6, b6qk, K6, nullptr,
                                         qkv, 3 * CDIM, MROWS, K6 / BKE);
    }
    // --- GEMM1b (v): bf16x3 ---
    {
        dim3 grid(CDIM / BN, (MROWS + BM - 1) / BM);       // (8, 65)
        tc_gemm<<<grid, 256, DYN_SMEM>>>(a3, KT3, b3v, KT3, nullptr,
                                         qkv + 2 * CDIM, 3 * CDIM, MROWS, KT3 / BKE);
    }
    router_pool_kernel<<<BATCH * MEXP, 256>>>();
    {
        dim3 grid((NTOK + LT - 1) / LT, BH);               // (17, 128)
        logits_kernel<<<grid, 256>>>();
    }
    softmax_topk_kernel<<<BH * MEXP, 256>>>();
    {
        dim3 grid(BH, 4);
        agent_value_part<<<grid, 256>>>();
    }
    agent_value_reduce<<<(BH * MEXP * HDIM + 255) / 256, 256>>>();
    {
        dim3 grid((NTOK + TQ - 1) / TQ, BH);
        attn_kernel<<<grid, 256>>>();
    }
    // --- GEMM2: out = attn @ Wproj + b (bf16x3) ---
    split3_rows<<<(MROWS * CDIM + 255) / 256, 256>>>(attn, a3, MROWS * CDIM);
    {
        dim3 g(CDIM / 32, CDIM / 32);
        transpose_split3<<<g, 256>>>(Wproj, CDIM, b3p);
    }
    {
        dim3 grid(CDIM / BN, (MROWS + BM - 1) / BM);       // (8, 65)
        tc_gemm<<<grid, 256, DYN_SMEM>>>(a3, KT3, b3p, KT3, bproj,
                                         out, CDIM, MROWS, KT3 / BKE);
    }
}

// round 10
// speedup vs baseline: 1.5499x; 1.5499x over previous
#include <cuda_runtime.h>
#include <cuda_bf16.h>
#include <math_constants.h>
#include <cstdint>

// ---------------------------------------------------------------------------
// MiTA Attention. compute_103 PTX target (no tcgen05) -> mma.sync HMMA bf16.
// q/k via bf16x6 split (err ~1e-7, decision-safe); v & proj via bf16x3.
// Round 10: single-sync GEMM mainloop, merged qkv GEMM launch, attn->A'3 fused.
// ---------------------------------------------------------------------------

#define BATCH 8
#define NTOK 1025
#define CDIM 1024
#define HEADS 16
#define HDIM 64
#define MEXP 25
#define KSEL 25
#define GRID 32
#define POOLN 5
#define SCALE 0.125f
#define MROWS (BATCH * NTOK)       // 8200
#define BH (BATCH * HEADS)         // 128
#define K6 (6 * CDIM)              // 6144
#define KT3 (3 * CDIM)             // 3072

// ---------------- scratch ----------------
__device__ float g_qkv[BATCH * NTOK * 3 * CDIM];
__device__ float g_router[BATCH * MEXP * CDIM];
__device__ float g_rlog[BH * MEXP * NTOK];
__device__ float g_gate[BH * MEXP * NTOK];        // layout [bh][m][n]
__device__ int   g_topk[BH * MEXP * KSEL];
__device__ float g_agentv[BH * MEXP * HDIM];
__device__ float g_avpart[4][BH * MEXP * HDIM];
__device__ __nv_bfloat16 g_a6[MROWS * K6];        // A'6 for GEMM1a
__device__ __nv_bfloat16 g_a3[MROWS * KT3];       // A'3: GEMM1b input, then attn output
__device__ __nv_bfloat16 g_b6qk[2 * CDIM * K6];
__device__ __nv_bfloat16 g_b3v[CDIM * KT3];
__device__ __nv_bfloat16 g_b3p[CDIM * KT3];

// ======================= helpers ===========================================
__device__ __forceinline__ uint32_t smem_u32(const void* p) {
    uint32_t a;
    asm("{ .reg .u64 t; cvta.to.shared.u64 t, %1; cvt.u32.u64 %0, t; }" : "=r"(a) : "l"(p));
    return a;
}
#define CP16(dst, src, nbytes) \
    asm volatile("cp.async.cg.shared.global [%0], [%1], 16, %2;" \
        :: "r"(dst), "l"(src), "r"(nbytes) : "memory")

__device__ __forceinline__ void ldmx4(uint32_t& r0, uint32_t& r1, uint32_t& r2,
                                      uint32_t& r3, uint32_t addr) {
    asm volatile("ldmatrix.sync.aligned.m8n8.x4.shared.b16 {%0,%1,%2,%3}, [%4];"
        : "=r"(r0), "=r"(r1), "=r"(r2), "=r"(r3) : "r"(addr));
}
__device__ __forceinline__ void mma16816(float* c, const uint32_t* a,
                                         uint32_t b0, uint32_t b1) {
    asm volatile(
        "mma.sync.aligned.m16n8k16.row.col.f32.bf16.bf16.f32 "
        "{%0,%1,%2,%3}, {%4,%5,%6,%7}, {%8,%9}, {%0,%1,%2,%3};"
        : "+f"(c[0]), "+f"(c[1]), "+f"(c[2]), "+f"(c[3])
        : "r"(a[0]), "r"(a[1]), "r"(a[2]), "r"(a[3]), "r"(b0), "r"(b1));
}

// ======================= HMMA GEMM body ====================================
#define BM 128
#define BN 128
#define BKE 64
#define STAGES 3
#define TILE_BYTES (128 * 128)
#define SM_A 0
#define SM_B (STAGES * TILE_BYTES)
#define DYN_SMEM (2 * STAGES * TILE_BYTES + 1024)

__device__ __forceinline__ void load_tile(
    const __nv_bfloat16* __restrict__ A, int lda,
    const __nv_bfloat16* __restrict__ Bt, int ldb,
    int Mrows, int rowBase, int colBase, int kt, int buf, uint32_t sb, int tid)
{
    const int k0 = kt * BKE;
    #pragma unroll
    for (int j = 0; j < 4; j++) {
        int i = tid + 256 * j;
        int r = i >> 3, c = i & 7;
        uint32_t dst = sb + SM_A + buf * TILE_BYTES
                     + r * 128 + ((c * 16) ^ ((r & 7) * 16));
        bool ok = (rowBase + r) < Mrows;
        const __nv_bfloat16* src = ok ? (A + (size_t)(rowBase + r) * lda + k0 + c * 8) : A;
        CP16(dst, src, ok ? 16 : 0);
    }
    #pragma unroll
    for (int j = 0; j < 4; j++) {
        int i = tid + 256 * j;
        int r = i >> 3, c = i & 7;
        uint32_t dst = sb + SM_B + buf * TILE_BYTES
                     + r * 128 + ((c * 16) ^ ((r & 7) * 16));
        const __nv_bfloat16* src = Bt + (size_t)(colBase + r) * ldb + k0 + c * 8;
        CP16(dst, src, 16);
    }
    asm volatile("cp.async.commit_group;" ::: "memory");
}

__device__ __forceinline__ void gemm_body(
    const __nv_bfloat16* __restrict__ A, int lda,
    const __nv_bfloat16* __restrict__ Bt, int ldb,
    const float* __restrict__ bias, float* __restrict__ C, int ldc,
    int Mrows, int nkt, int rowBase, int colBase, uint32_t sb, int tid)
{
    const int lane = tid & 31, w = tid >> 5;
    const int wm = w >> 1, wn = w & 1;

    const uint32_t xm = (lane & 7) * 16;
    uint32_t aRow[2];
    #pragma unroll
    for (int mi = 0; mi < 2; mi++)
        aRow[mi] = (uint32_t)(wm * 32 + mi * 16 + (lane & 15)) * 128u;
    const uint32_t aCol = 16u * (lane >> 4);
    uint32_t bRow[4];
    #pragma unroll
    for (int p = 0; p < 4; p++)
        bRow[p] = (uint32_t)(wn * 64 + p * 16 + (lane & 7) + 8 * (lane >> 4)) * 128u;
    const uint32_t bCol = 16u * ((lane >> 3) & 1);

    float acc[2][8][4];
    #pragma unroll
    for (int mi = 0; mi < 2; mi++)
        #pragma unroll
        for (int ni = 0; ni < 8; ni++)
            #pragma unroll
            for (int r = 0; r < 4; r++) acc[mi][ni][r] = 0.f;

    // prologue: 2 stages in flight
    load_tile(A, lda, Bt, ldb, Mrows, rowBase, colBase, 0, 0, sb, tid);
    load_tile(A, lda, Bt, ldb, Mrows, rowBase, colBase, 1, 1, sb, tid);

    for (int kt = 0; kt < nkt; kt++) {
        if (kt == nkt - 1) asm volatile("cp.async.wait_group 0;" ::: "memory");
        else               asm volatile("cp.async.wait_group 1;" ::: "memory");
        __syncthreads();   // all warps done with slot (kt+2)%3's previous occupant

        if (kt + 2 < nkt)
            load_tile(A, lda, Bt, ldb, Mrows, rowBase, colBase,
                      kt + 2, (kt + 2) % STAGES, sb, tid);

        const int buf = kt % STAGES;
        const uint32_t baseA = sb + SM_A + buf * TILE_BYTES;
        const uint32_t baseB = sb + SM_B + buf * TILE_BYTES;
        #pragma unroll
        for (int kf = 0; kf < 4; kf++) {
            const uint32_t kb = kf * 32;
            uint32_t af[2][4], bf[8][2];
            #pragma unroll
            for (int mi = 0; mi < 2; mi++)
                ldmx4(af[mi][0], af[mi][1], af[mi][2], af[mi][3],
                      baseA + aRow[mi] + ((kb + aCol) ^ xm));
            #pragma unroll
            for (int p = 0; p < 4; p++)
                ldmx4(bf[2 * p][0], bf[2 * p][1], bf[2 * p + 1][0], bf[2 * p + 1][1],
                      baseB + bRow[p] + ((kb + bCol) ^ xm));
            #pragma unroll
            for (int mi = 0; mi < 2; mi++)
                #pragma unroll
                for (int ni = 0; ni < 8; ni++)
                    mma16816(acc[mi][ni], af[mi], bf[ni][0], bf[ni][1]);
        }
    }

    const int colW = colBase + wn * 64 + 2 * (lane & 3);
    #pragma unroll
    for (int mi = 0; mi < 2; mi++) {
        int r0 = rowBase + wm * 32 + mi * 16 + (lane >> 2);
        #pragma unroll
        for (int ni = 0; ni < 8; ni++) {
            int col = colW + ni * 8;
            float bx = 0.f, by = 0.f;
            if (bias) { bx = bias[col]; by = bias[col + 1]; }
            if (r0 < Mrows)
                *(float2*)&C[(size_t)r0 * ldc + col] =
                    make_float2(acc[mi][ni][0] + bx, acc[mi][ni][1] + by);
            if (r0 + 8 < Mrows)
                *(float2*)&C[(size_t)(r0 + 8) * ldc + col] =
                    make_float2(acc[mi][ni][2] + bx, acc[mi][ni][3] + by);
        }
    }
}

// Merged GEMM1a (q,k bf16x6, 16 col-tiles) + GEMM1b (v bf16x3, 8 col-tiles).
__global__ __launch_bounds__(256, 2) void gemm_qkv()
{
    extern __shared__ char dsm[];
    uint32_t sb = (smem_u32(dsm) + 1023u) & ~1023u;
    const int tid = threadIdx.x;
    const int rowBase = blockIdx.y * BM;
    if (blockIdx.x < 16) {
        gemm_body(g_a6, K6, g_b6qk, K6, nullptr, g_qkv, 3 * CDIM,
                  MROWS, K6 / BKE, rowBase, blockIdx.x * BN, sb, tid);
    } else {
        gemm_body(g_a3, KT3, g_b3v, KT3, nullptr, g_qkv + 2 * CDIM, 3 * CDIM,
                  MROWS, KT3 / BKE, rowBase, (blockIdx.x - 16) * BN, sb, tid);
    }
}

// Generic GEMM (used for GEMM2).
__global__ __launch_bounds__(256, 2) void tc_gemm(
    const __nv_bfloat16* __restrict__ A, int lda,
    const __nv_bfloat16* __restrict__ Bt, int ldb,
    const float* __restrict__ bias, float* __restrict__ C, int ldc,
    int Mrows, int nkt)
{
    extern __shared__ char dsm[];
    uint32_t sb = (smem_u32(dsm) + 1023u) & ~1023u;
    gemm_body(A, lda, Bt, ldb, bias, C, ldc, Mrows, nkt,
              blockIdx.y * BM, blockIdx.x * BN, sb, threadIdx.x);
}

// ======================= split / transpose conversions =====================
// Fused: one read of src -> A'6 = [Ah|Ah|Al|Ah|Am|Am] AND A'3 = [Ah|Ah|Am]
__global__ __launch_bounds__(256) void split63_rows(
    const float* __restrict__ src, __nv_bfloat16* __restrict__ d6,
    __nv_bfloat16* __restrict__ d3, int total)
{
    int idx = blockIdx.x * 256 + threadIdx.x;
    if (idx >= total) return;
    int r = idx >> 10, k = idx & 1023;
    float v = src[idx];
    __nv_bfloat16 h = __float2bfloat16(v);
    float r1 = v - __bfloat162float(h);
    __nv_bfloat16 m = __float2bfloat16(r1);
    __nv_bfloat16 l = __float2bfloat16(r1 - __bfloat162float(m));
    size_t o6 = (size_t)r * K6 + k;
    d6[o6] = h;
    d6[o6 + 1024] = h;
    d6[o6 + 2048] = l;
    d6[o6 + 3072] = h;
    d6[o6 + 4096] = m;
    d6[o6 + 5120] = m;
    size_t o3 = (size_t)r * KT3 + k;
    d3[o3] = h;
    d3[o3 + 1024] = h;
    d3[o3 + 2048] = m;
}

__global__ __launch_bounds__(256) void transpose_split6(
    const float* __restrict__ W, int ldw, __nv_bfloat16* __restrict__ Bt)
{
    __shared__ float t[32][33];
    int n0 = blockIdx.x * 32, k0 = blockIdx.y * 32;
    int tx = threadIdx.x & 31, ty = threadIdx.x >> 5;
    #pragma unroll
    for (int i = 0; i < 32; i += 8)
        t[ty + i][tx] = W[(size_t)(k0 + ty + i) * ldw + n0 + tx];
    __syncthreads();
    #pragma unroll
    for (int i = 0; i < 32; i += 8) {
        int n = n0 + ty + i, k = k0 + tx;
        float v = t[tx][ty + i];
        __nv_bfloat16 h = __float2bfloat16(v);
        float r1 = v - __bfloat162float(h);
        __nv_bfloat16 m = __float2bfloat16(r1);
        __nv_bfloat16 l = __float2bfloat16(r1 - __bfloat162float(m));
        size_t o = (size_t)n * K6 + k;
        Bt[o] = h;
        Bt[o + 1024] = m;
        Bt[o + 2048] = h;
        Bt[o + 3072] = l;
        Bt[o + 4096] = h;
        Bt[o + 5120] = m;
    }
}

__global__ __launch_bounds__(256) void transpose_split3(
    const float* __restrict__ W, int ldw, __nv_bfloat16* __restrict__ Bt)
{
    __shared__ float t[32][33];
    int n0 = blockIdx.x * 32, k0 = blockIdx.y * 32;
    int tx = threadIdx.x & 31, ty = threadIdx.x >> 5;
    #pragma unroll
    for (int i = 0; i < 32; i += 8)
        t[ty + i][tx] = W[(size_t)(k0 + ty + i) * ldw + n0 + tx];
    __syncthreads();
    #pragma unroll
    for (int i = 0; i < 32; i += 8) {
        int n = n0 + ty + i, k = k0 + tx;
        float v = t[tx][ty + i];
        __nv_bfloat16 h = __float2bfloat16(v);
        __nv_bfloat16 m = __float2bfloat16(v - __bfloat162float(h));
        size_t o = (size_t)n * KT3 + k;
        Bt[o] = h;
        Bt[o + 1024] = m;
        Bt[o + 2048] = h;
    }
}

// ======================= small pipeline kernels ============================
__global__ void router_pool_kernel()
{
    int blk = blockIdx.x;
    int b = blk / MEXP, m = blk % MEXP;
    int p = m / POOLN, q = m % POOLN;
    int hs = (p * GRID) / POOLN, he = ((p + 1) * GRID + POOLN - 1) / POOLN;
    int ws = (q * GRID) / POOLN, we = ((q + 1) * GRID + POOLN - 1) / POOLN;
    float inv = 1.0f / (float)((he - hs) * (we - ws));
    for (int c = threadIdx.x; c < CDIM; c += blockDim.x) {
        float s = 0.f;
        for (int h = hs; h < he; h++)
            for (int w = ws; w < we; w++)
                s += g_qkv[((size_t)(b * NTOK + h * GRID + w)) * (3 * CDIM) + c];
        g_router[(size_t)blk * CDIM + c] = s * inv;
    }
}

// logits: smem-staged, coalesced. Block = (64-token tile, bh), 256 threads.
#define LT 64
__global__ __launch_bounds__(256) void logits_kernel()
{
    __shared__ float q_s[LT][65];
    __shared__ float k_s[LT][65];
    __shared__ float r_s[MEXP][65];

    int bh = blockIdx.y;
    int b = bh / HEADS, h = bh % HEADS;
    int n0 = blockIdx.x * LT;
    int tid = threadIdx.x;

    for (int i = tid; i < MEXP * 16; i += 256) {
        int m = i >> 4, c = (i & 15) * 4;
        float4 v = *(const float4*)&g_router[(size_t)(b * MEXP + m) * CDIM + h * HDIM + c];
        r_s[m][c] = v.x; r_s[m][c + 1] = v.y; r_s[m][c + 2] = v.z; r_s[m][c + 3] = v.w;
    }
    #pragma unroll
    for (int it = 0; it < 4; it++) {
        int i = tid + it * 256;
        int row = i >> 4, c = (i & 15) * 4;
        int n = n0 + row;
        float4 qv = make_float4(0.f, 0.f, 0.f, 0.f), kv = qv;
        if (n < NTOK) {
            const float* base = &g_qkv[(size_t)(b * NTOK + n) * (3 * CDIM) + h * HDIM + c];
            qv = *(const float4*)base;
            kv = *(const float4*)(base + CDIM);
        }
        q_s[row][c] = qv.x; q_s[row][c + 1] = qv.y; q_s[row][c + 2] = qv.z; q_s[row][c + 3] = qv.w;
        k_s[row][c] = kv.x; k_s[row][c + 1] = kv.y; k_s[row][c + 2] = kv.z; k_s[row][c + 3] = kv.w;
    }
    __syncthreads();

    const int nl = tid & 63;
    const int g = tid >> 6;
    float acck[7], accq[7];
    #pragma unroll
    for (int j = 0; j < 7; j++) { acck[j] = 0.f; accq[j] = 0.f; }

    for (int d = 0; d < HDIM; d++) {
        float qv = q_s[nl][d];
        float kv = k_s[nl][d];
        #pragma unroll
        for (int j = 0; j < 7; j++) {
            int m = g + 4 * j;
            int mc = (m < MEXP) ? m : 0;
            float r = r_s[mc][d];
            acck[j] += r * kv;
            accq[j] += r * qv;
        }
    }
    int n = n0 + nl;
    if (n < NTOK) {
        #pragma unroll
        for (int j = 0; j < 7; j++) {
            int m = g + 4 * j;
            if (m < MEXP) {
                size_t o = ((size_t)(bh * MEXP + m)) * NTOK + n;
                g_rlog[o] = acck[j];
                g_gate[o] = accq[j];
            }
        }
    }
}

__global__ __launch_bounds__(256) void softmax_topk_kernel()
{
    __shared__ float swv[8];
    __shared__ int   swi[8];
    __shared__ float selv[KSEL];
    __shared__ int   seli[KSEL];
    __shared__ float s_inv;

    int row = blockIdx.x;
    float* r = &g_rlog[(size_t)row * NTOK];
    int tid = threadIdx.x, lane = tid & 31, wid = tid >> 5;

    float vals[5];
    #pragma unroll
    for (int i = 0; i < 5; i++) {
        int n = tid + (i << 8);
        vals[i] = (n < NTOK) ? r[n] : -CUDART_INF_F;
    }

    for (int it = 0; it < KSEL; it++) {
        float bv = -CUDART_INF_F; int bi = 0x7FFFFFFF;
        #pragma unroll
        for (int i = 0; i < 5; i++) {
            int n = tid + (i << 8);
            float v = vals[i];
            if (v > bv || (v == bv && n < bi)) { bv = v; bi = n; }
        }
        #pragma unroll
        for (int off = 16; off > 0; off >>= 1) {
            float ov = __shfl_xor_sync(0xFFFFFFFFu, bv, off);
            int   oi = __shfl_xor_sync(0xFFFFFFFFu, bi, off);
            if (ov > bv || (ov == bv && oi < bi)) { bv = ov; bi = oi; }
        }
        if (lane == 0) { swv[wid] = bv; swi[wid] = bi; }
        __syncthreads();
        if (tid == 0) {
            float gv = swv[0]; int gi = swi[0];
            #pragma unroll
            for (int ww = 1; ww < 8; ww++)
                if (swv[ww] > gv || (swv[ww] == gv && swi[ww] < gi)) { gv = swv[ww]; gi = swi[ww]; }
            selv[it] = gv; seli[it] = gi;
        }
        __syncthreads();
        int sn = seli[it];
        if (tid == (sn & 255)) vals[sn >> 8] = -CUDART_INF_F;
    }

    if (tid < KSEL) g_topk[(size_t)row * KSEL + tid] = seli[tid];
    float mx = selv[0];
    for (int it = 0; it < KSEL; it++) {
        int sn = seli[it];
        if (tid == (sn & 255)) vals[sn >> 8] = selv[it];
    }

    float ev[5];
    float psum = 0.f;
    #pragma unroll
    for (int i = 0; i < 5; i++) {
        int n = tid + (i << 8);
        float e = (n < NTOK) ? __expf((vals[i] - mx) * SCALE) : 0.f;
        ev[i] = e;
        psum += e;
    }
    #pragma unroll
    for (int off = 16; off > 0; off >>= 1)
        psum += __shfl_xor_sync(0xFFFFFFFFu, psum, off);
    if (lane == 0) swv[wid] = psum;
    __syncthreads();
    if (tid == 0) {
        float s = 0.f;
        #pragma unroll
        for (int ww = 0; ww < 8; ww++) s += swv[ww];
        s_inv = 1.0f / s;
    }
    __syncthreads();
    float inv = s_inv;
    #pragma unroll
    for (int i = 0; i < 5; i++) {
        int n = tid + (i << 8);
        if (n < NTOK) r[n] = ev[i] * inv;
    }
}

// agent_value split 4 ways over tokens; deterministic two-phase reduce.
#define AV_TILES 33
__global__ __launch_bounds__(256) void agent_value_part()
{
    __shared__ float p_s[MEXP][32];
    __shared__ float v_s[32][HDIM];
    int bh = blockIdx.x;
    int ch = blockIdx.y;
    int b = bh / HEADS, h = bh % HEADS;
    int tid = threadIdx.x;
    int tile0 = ch * 9;
    int tile1 = tile0 + 9; if (tile1 > AV_TILES) tile1 = AV_TILES;

    float acc[7];
    #pragma unroll
    for (int i = 0; i < 7; i++) acc[i] = 0.f;

    for (int tile = tile0; tile < tile1; tile++) {
        int t0 = tile * 32;
        for (int e = tid; e < MEXP * 32; e += 256) {
            int m = e / 32, n = e % 32;
            p_s[m][n] = (t0 + n < NTOK)
                ? g_rlog[((size_t)(bh * MEXP + m)) * NTOK + t0 + n] : 0.f;
        }
        for (int e = tid; e < 32 * HDIM; e += 256) {
            int n = e / HDIM, d = e % HDIM;
            v_s[n][d] = (t0 + n < NTOK)
                ? g_qkv[(size_t)(b * NTOK + t0 + n) * (3 * CDIM) + 2 * CDIM + h * HDIM + d]
                : 0.f;
        }
        __syncthreads();
        for (int n = 0; n < 32; n++) {
            #pragma unroll
            for (int i = 0; i < 7; i++) {
                int pidx = tid + 256 * i;
                if (pidx < MEXP * HDIM) {
                    int m = pidx >> 6, d = pidx & 63;
                    acc[i] += p_s[m][n] * v_s[n][d];
                }
            }
        }
        __syncthreads();
    }
    #pragma unroll
    for (int i = 0; i < 7; i++) {
        int pidx = tid + 256 * i;
        if (pidx < MEXP * HDIM)
            g_avpart[ch][(size_t)bh * MEXP * HDIM + pidx] = acc[i];
    }
}

__global__ __launch_bounds__(256) void agent_value_reduce()
{
    int idx = blockIdx.x * 256 + threadIdx.x;
    if (idx < BH * MEXP * HDIM)
        g_agentv[idx] = g_avpart[0][idx] + g_avpart[1][idx]
                      + g_avpart[2][idx] + g_avpart[3][idx];
}

// Final mixed attention; writes A'3 = [h|h|m] bf16 directly (GEMM2 input).
#define TQ 16
__global__ __launch_bounds__(256) void attn_kernel()
{
    __shared__ float ag_s[MEXP][HDIM];
    __shared__ float q_s[TQ][HDIM];
    __shared__ float w_s[TQ][65];
    __shared__ int   sel_s[TQ][KSEL];

    int bh = blockIdx.y;
    int b = bh / HEADS, h = bh % HEADS;
    int n0 = blockIdx.x * TQ;
    int tid = threadIdx.x;

    for (int e = tid; e < MEXP * HDIM; e += 256)
        ((float*)ag_s)[e] = g_agentv[(size_t)bh * MEXP * HDIM + e];
    for (int e = tid; e < TQ * HDIM; e += 256) {
        int qi = e / HDIM, d = e % HDIM;
        int n = n0 + qi;
        q_s[qi][d] = (n < NTOK)
            ? g_qkv[(size_t)(b * NTOK + n) * (3 * CDIM) + h * HDIM + d] : 0.f;
    }
    __syncthreads();

    if (tid < TQ && n0 + tid < NTOK) {
        const float* gb = &g_gate[(size_t)bh * MEXP * NTOK + n0 + tid];
        float best = -CUDART_INF_F; int ei = 0;
        #pragma unroll
        for (int m = 0; m < MEXP; m++) {
            float v = gb[(size_t)m * NTOK];
            w_s[tid][m] = v * SCALE;
            if (v > best) { best = v; ei = m; }
        }
        const int* tk = &g_topk[((size_t)(bh * MEXP + ei)) * KSEL];
        #pragma unroll
        for (int k = 0; k < KSEL; k++) sel_s[tid][k] = tk[k];
    }
    __syncthreads();

    int warp = tid >> 5, lane = tid & 31;
    for (int task = warp; task < TQ * KSEL; task += 8) {
        int qi = task / KSEL, k = task % KSEL;
        if (n0 + qi < NTOK) {
            int key = sel_s[qi][k];
            const float2* kp = (const float2*)
                &g_qkv[(size_t)(b * NTOK + key) * (3 * CDIM) + CDIM + h * HDIM];
            float2 kv = kp[lane];
            float2 qv = *(const float2*)&q_s[qi][2 * lane];
            float s = qv.x * kv.x + qv.y * kv.y;
            #pragma unroll
            for (int off = 16; off > 0; off >>= 1)
                s += __shfl_xor_sync(0xFFFFFFFFu, s, off);
            if (lane == 0) w_s[qi][MEXP + k] = s * SCALE;
        }
    }
    __syncthreads();

    if (tid < TQ && n0 + tid < NTOK) {
        float mx = -CUDART_INF_F;
        #pragma unroll
        for (int j = 0; j < MEXP + KSEL; j++) mx = fmaxf(mx, w_s[tid][j]);
        float sum = 0.f;
        #pragma unroll
        for (int j = 0; j < MEXP + KSEL; j++) {
            float e = __expf(w_s[tid][j] - mx);
            w_s[tid][j] = e;
            sum += e;
        }
        float inv = 1.0f / sum;
        #pragma unroll
        for (int j = 0; j < MEXP + KSEL; j++) w_s[tid][j] *= inv;
    }
    __syncthreads();

    int d = tid & 63;
    #pragma unroll
    for (int i = 0; i < 4; i++) {
        int qi = (tid >> 6) + i * 4;
        int n = n0 + qi;
        if (n < NTOK) {
            float o = 0.f;
            #pragma unroll
            for (int m = 0; m < MEXP; m++) o += w_s[qi][m] * ag_s[m][d];
            #pragma unroll
            for (int k = 0; k < KSEL; k++) {
                int key = sel_s[qi][k];
                o += w_s[qi][MEXP + k] *
                     g_qkv[(size_t)(b * NTOK + key) * (3 * CDIM) + 2 * CDIM + h * HDIM + d];
            }
            // write A'3 = [h|h|m] directly
            __nv_bfloat16 hh = __float2bfloat16(o);
            __nv_bfloat16 mm = __float2bfloat16(o - __bfloat162float(hh));
            size_t o3 = (size_t)(b * NTOK + n) * KT3 + h * HDIM + d;
            g_a3[o3] = hh;
            g_a3[o3 + 1024] = hh;
            g_a3[o3 + 2048] = mm;
        }
    }
}

// ---------------------------------------------------------------------------
extern "C" void kernel_launch(void* const* d_in, const int* in_sizes, int n_in,
                              void* d_out, int out_size)
{
    const float* x     = (const float*)d_in[0];
    const float* Wqkv  = (const float*)d_in[1];
    const float* Wproj = (const float*)d_in[2];
    const float* bproj = (const float*)d_in[3];
    float* out = (float*)d_out;

    __nv_bfloat16* a6;   cudaGetSymbolAddress((void**)&a6,   g_a6);
    __nv_bfloat16* a3;   cudaGetSymbolAddress((void**)&a3,   g_a3);
    __nv_bfloat16* b6qk; cudaGetSymbolAddress((void**)&b6qk, g_b6qk);
    __nv_bfloat16* b3v;  cudaGetSymbolAddress((void**)&b3v,  g_b3v);
    __nv_bfloat16* b3p;  cudaGetSymbolAddress((void**)&b3p,  g_b3p);

    cudaFuncSetAttribute(tc_gemm,  cudaFuncAttributeMaxDynamicSharedMemorySize, DYN_SMEM);
    cudaFuncSetAttribute(gemm_qkv, cudaFuncAttributeMaxDynamicSharedMemorySize, DYN_SMEM);

    // --- conversions for GEMM1 (A'6 + A'3 in one pass over x) ---
    split63_rows<<<(MROWS * CDIM + 255) / 256, 256>>>(x, a6, a3, MROWS * CDIM);
    {
        dim3 g(2 * CDIM / 32, CDIM / 32);
        transpose_split6<<<g, 256>>>(Wqkv, 3 * CDIM, b6qk);           // q,k columns
    }
    {
        dim3 g(CDIM / 32, CDIM / 32);
        transpose_split3<<<g, 256>>>(Wqkv + 2 * CDIM, 3 * CDIM, b3v); // v columns
    }
    // --- GEMM1 (q,k bf16x6 + v bf16x3, one merged launch) ---
    {
        dim3 grid(24, (MROWS + BM - 1) / BM);              // (24, 65)
        gemm_qkv<<<grid, 256, DYN_SMEM>>>();
    }
    router_pool_kernel<<<BATCH * MEXP, 256>>>();
    {
        dim3 grid((NTOK + LT - 1) / LT, BH);               // (17, 128)
        logits_kernel<<<grid, 256>>>();
    }
    softmax_topk_kernel<<<BH * MEXP, 256>>>();
    {
        dim3 grid(BH, 4);
        agent_value_part<<<grid, 256>>>();
    }
    agent_value_reduce<<<(BH * MEXP * HDIM + 255) / 256, 256>>>();
    {
        dim3 grid((NTOK + TQ - 1) / TQ, BH);
        attn_kernel<<<grid, 256>>>();                      // writes A'3
    }
    // --- GEMM2: out = attn @ Wproj + b (bf16x3) ---
    {
        dim3 g(CDIM / 32, CDIM / 32);
        transpose_split3<<<g, 256>>>(Wproj, CDIM, b3p);
    }
    {
        dim3 grid(CDIM / BN, (MROWS + BM - 1) / BM);       // (8, 65)
        tc_gemm<<<grid, 256, DYN_SMEM>>>(a3, KT3, b3p, KT3, bproj,
                                         out, CDIM, MROWS, KT3 / BKE);
    }
}

// round 12
// speedup vs baseline: 1.8581x; 1.1989x over previous
#include <cuda_runtime.h>
#include <cuda_bf16.h>
#include <math_constants.h>
#include <cstdint>

// ---------------------------------------------------------------------------
// MiTA Attention. compute_103 PTX target (no tcgen05) -> mma.sync HMMA bf16.
// q/k via bf16x6 split (err ~1e-7, decision-safe); v & proj via bf16x3.
// Round 11: expert-grouped mixed attention (smem-resident K/V per expert).
// ---------------------------------------------------------------------------

#define BATCH 8
#define NTOK 1025
#define CDIM 1024
#define HEADS 16
#define HDIM 64
#define MEXP 25
#define KSEL 25
#define GRID 32
#define POOLN 5
#define SCALE 0.125f
#define MROWS (BATCH * NTOK)       // 8200
#define BH (BATCH * HEADS)         // 128
#define K6 (6 * CDIM)              // 6144
#define KT3 (3 * CDIM)             // 3072

// ---------------- scratch ----------------
__device__ float g_qkv[BATCH * NTOK * 3 * CDIM];
__device__ float g_router[BATCH * MEXP * CDIM];
__device__ float g_rlog[BH * MEXP * NTOK];
__device__ float g_gate[BH * MEXP * NTOK];        // layout [bh][m][n]
__device__ int   g_topk[BH * MEXP * KSEL];
__device__ float g_agentv[BH * MEXP * HDIM];
__device__ float g_avpart[4][BH * MEXP * HDIM];
__device__ int   g_cnt[BH * MEXP];                // queries per (bh, expert)
__device__ int   g_qlist[BH * MEXP * NTOK];       // bucketed query indices
__device__ __nv_bfloat16 g_a6[MROWS * K6];
__device__ __nv_bfloat16 g_a3[MROWS * KT3];       // A'3: GEMM1b in, attn out
__device__ __nv_bfloat16 g_b6qk[2 * CDIM * K6];
__device__ __nv_bfloat16 g_b3v[CDIM * KT3];
__device__ __nv_bfloat16 g_b3p[CDIM * KT3];

// ======================= helpers ===========================================
__device__ __forceinline__ uint32_t smem_u32(const void* p) {
    uint32_t a;
    asm("{ .reg .u64 t; cvta.to.shared.u64 t, %1; cvt.u32.u64 %0, t; }" : "=r"(a) : "l"(p));
    return a;
}
#define CP16(dst, src, nbytes) \
    asm volatile("cp.async.cg.shared.global [%0], [%1], 16, %2;" \
        :: "r"(dst), "l"(src), "r"(nbytes) : "memory")

__device__ __forceinline__ void ldmx4(uint32_t& r0, uint32_t& r1, uint32_t& r2,
                                      uint32_t& r3, uint32_t addr) {
    asm volatile("ldmatrix.sync.aligned.m8n8.x4.shared.b16 {%0,%1,%2,%3}, [%4];"
        : "=r"(r0), "=r"(r1), "=r"(r2), "=r"(r3) : "r"(addr));
}
__device__ __forceinline__ void mma16816(float* c, const uint32_t* a,
                                         uint32_t b0, uint32_t b1) {
    asm volatile(
        "mma.sync.aligned.m16n8k16.row.col.f32.bf16.bf16.f32 "
        "{%0,%1,%2,%3}, {%4,%5,%6,%7}, {%8,%9}, {%0,%1,%2,%3};"
        : "+f"(c[0]), "+f"(c[1]), "+f"(c[2]), "+f"(c[3])
        : "r"(a[0]), "r"(a[1]), "r"(a[2]), "r"(a[3]), "r"(b0), "r"(b1));
}

// ======================= HMMA GEMM body ====================================
#define BM 128
#define BN 128
#define BKE 64
#define STAGES 3
#define TILE_BYTES (128 * 128)
#define SM_A 0
#define SM_B (STAGES * TILE_BYTES)
#define DYN_SMEM (2 * STAGES * TILE_BYTES + 1024)

__device__ __forceinline__ void load_tile(
    const __nv_bfloat16* __restrict__ A, int lda,
    const __nv_bfloat16* __restrict__ Bt, int ldb,
    int Mrows, int rowBase, int colBase, int kt, int buf, uint32_t sb, int tid)
{
    const int k0 = kt * BKE;
    #pragma unroll
    for (int j = 0; j < 4; j++) {
        int i = tid + 256 * j;
        int r = i >> 3, c = i & 7;
        uint32_t dst = sb + SM_A + buf * TILE_BYTES
                     + r * 128 + ((c * 16) ^ ((r & 7) * 16));
        bool ok = (rowBase + r) < Mrows;
        const __nv_bfloat16* src = ok ? (A + (size_t)(rowBase + r) * lda + k0 + c * 8) : A;
        CP16(dst, src, ok ? 16 : 0);
    }
    #pragma unroll
    for (int j = 0; j < 4; j++) {
        int i = tid + 256 * j;
        int r = i >> 3, c = i & 7;
        uint32_t dst = sb + SM_B + buf * TILE_BYTES
                     + r * 128 + ((c * 16) ^ ((r & 7) * 16));
        const __nv_bfloat16* src = Bt + (size_t)(colBase + r) * ldb + k0 + c * 8;
        CP16(dst, src, 16);
    }
    asm volatile("cp.async.commit_group;" ::: "memory");
}

__device__ __forceinline__ void gemm_body(
    const __nv_bfloat16* __restrict__ A, int lda,
    const __nv_bfloat16* __restrict__ Bt, int ldb,
    const float* __restrict__ bias, float* __restrict__ C, int ldc,
    int Mrows, int nkt, int rowBase, int colBase, uint32_t sb, int tid)
{
    const int lane = tid & 31, w = tid >> 5;
    const int wm = w >> 1, wn = w & 1;

    const uint32_t xm = (lane & 7) * 16;
    uint32_t aRow[2];
    #pragma unroll
    for (int mi = 0; mi < 2; mi++)
        aRow[mi] = (uint32_t)(wm * 32 + mi * 16 + (lane & 15)) * 128u;
    const uint32_t aCol = 16u * (lane >> 4);
    uint32_t bRow[4];
    #pragma unroll
    for (int p = 0; p < 4; p++)
        bRow[p] = (uint32_t)(wn * 64 + p * 16 + (lane & 7) + 8 * (lane >> 4)) * 128u;
    const uint32_t bCol = 16u * ((lane >> 3) & 1);

    float acc[2][8][4];
    #pragma unroll
    for (int mi = 0; mi < 2; mi++)
        #pragma unroll
        for (int ni = 0; ni < 8; ni++)
            #pragma unroll
            for (int r = 0; r < 4; r++) acc[mi][ni][r] = 0.f;

    load_tile(A, lda, Bt, ldb, Mrows, rowBase, colBase, 0, 0, sb, tid);
    load_tile(A, lda, Bt, ldb, Mrows, rowBase, colBase, 1, 1, sb, tid);

    for (int kt = 0; kt < nkt; kt++) {
        if (kt == nkt - 1) asm volatile("cp.async.wait_group 0;" ::: "memory");
        else               asm volatile("cp.async.wait_group 1;" ::: "memory");
        __syncthreads();

        if (kt + 2 < nkt)
            load_tile(A, lda, Bt, ldb, Mrows, rowBase, colBase,
                      kt + 2, (kt + 2) % STAGES, sb, tid);

        const int buf = kt % STAGES;
        const uint32_t baseA = sb + SM_A + buf * TILE_BYTES;
        const uint32_t baseB = sb + SM_B + buf * TILE_BYTES;
        #pragma unroll
        for (int kf = 0; kf < 4; kf++) {
            const uint32_t kb = kf * 32;
            uint32_t af[2][4], bf[8][2];
            #pragma unroll
            for (int mi = 0; mi < 2; mi++)
                ldmx4(af[mi][0], af[mi][1], af[mi][2], af[mi][3],
                      baseA + aRow[mi] + ((kb + aCol) ^ xm));
            #pragma unroll
            for (int p = 0; p < 4; p++)
                ldmx4(bf[2 * p][0], bf[2 * p][1], bf[2 * p + 1][0], bf[2 * p + 1][1],
                      baseB + bRow[p] + ((kb + bCol) ^ xm));
            #pragma unroll
            for (int mi = 0; mi < 2; mi++)
                #pragma unroll
                for (int ni = 0; ni < 8; ni++)
                    mma16816(acc[mi][ni], af[mi], bf[ni][0], bf[ni][1]);
        }
    }

    const int colW = colBase + wn * 64 + 2 * (lane & 3);
    #pragma unroll
    for (int mi = 0; mi < 2; mi++) {
        int r0 = rowBase + wm * 32 + mi * 16 + (lane >> 2);
        #pragma unroll
        for (int ni = 0; ni < 8; ni++) {
            int col = colW + ni * 8;
            float bx = 0.f, by = 0.f;
            if (bias) { bx = bias[col]; by = bias[col + 1]; }
            if (r0 < Mrows)
                *(float2*)&C[(size_t)r0 * ldc + col] =
                    make_float2(acc[mi][ni][0] + bx, acc[mi][ni][1] + by);
            if (r0 + 8 < Mrows)
                *(float2*)&C[(size_t)(r0 + 8) * ldc + col] =
                    make_float2(acc[mi][ni][2] + bx, acc[mi][ni][3] + by);
        }
    }
}

__global__ __launch_bounds__(256, 2) void gemm_qkv()
{
    extern __shared__ char dsm[];
    uint32_t sb = (smem_u32(dsm) + 1023u) & ~1023u;
    const int tid = threadIdx.x;
    const int rowBase = blockIdx.y * BM;
    if (blockIdx.x < 16) {
        gemm_body(g_a6, K6, g_b6qk, K6, nullptr, g_qkv, 3 * CDIM,
                  MROWS, K6 / BKE, rowBase, blockIdx.x * BN, sb, tid);
    } else {
        gemm_body(g_a3, KT3, g_b3v, KT3, nullptr, g_qkv + 2 * CDIM, 3 * CDIM,
                  MROWS, KT3 / BKE, rowBase, (blockIdx.x - 16) * BN, sb, tid);
    }
}

__global__ __launch_bounds__(256, 2) void tc_gemm(
    const __nv_bfloat16* __restrict__ A, int lda,
    const __nv_bfloat16* __restrict__ Bt, int ldb,
    const float* __restrict__ bias, float* __restrict__ C, int ldc,
    int Mrows, int nkt)
{
    extern __shared__ char dsm[];
    uint32_t sb = (smem_u32(dsm) + 1023u) & ~1023u;
    gemm_body(A, lda, Bt, ldb, bias, C, ldc, Mrows, nkt,
              blockIdx.y * BM, blockIdx.x * BN, sb, threadIdx.x);
}

// ======================= split / transpose conversions =====================
__global__ __launch_bounds__(256) void split63_rows(
    const float* __restrict__ src, __nv_bfloat16* __restrict__ d6,
    __nv_bfloat16* __restrict__ d3, int total)
{
    int idx = blockIdx.x * 256 + threadIdx.x;
    if (idx >= total) return;
    int r = idx >> 10, k = idx & 1023;
    float v = src[idx];
    __nv_bfloat16 h = __float2bfloat16(v);
    float r1 = v - __bfloat162float(h);
    __nv_bfloat16 m = __float2bfloat16(r1);
    __nv_bfloat16 l = __float2bfloat16(r1 - __bfloat162float(m));
    size_t o6 = (size_t)r * K6 + k;
    d6[o6] = h;
    d6[o6 + 1024] = h;
    d6[o6 + 2048] = l;
    d6[o6 + 3072] = h;
    d6[o6 + 4096] = m;
    d6[o6 + 5120] = m;
    size_t o3 = (size_t)r * KT3 + k;
    d3[o3] = h;
    d3[o3 + 1024] = h;
    d3[o3 + 2048] = m;
}

__global__ __launch_bounds__(256) void transpose_split6(
    const float* __restrict__ W, int ldw, __nv_bfloat16* __restrict__ Bt)
{
    __shared__ float t[32][33];
    int n0 = blockIdx.x * 32, k0 = blockIdx.y * 32;
    int tx = threadIdx.x & 31, ty = threadIdx.x >> 5;
    #pragma unroll
    for (int i = 0; i < 32; i += 8)
        t[ty + i][tx] = W[(size_t)(k0 + ty + i) * ldw + n0 + tx];
    __syncthreads();
    #pragma unroll
    for (int i = 0; i < 32; i += 8) {
        int n = n0 + ty + i, k = k0 + tx;
        float v = t[tx][ty + i];
        __nv_bfloat16 h = __float2bfloat16(v);
        float r1 = v - __bfloat162float(h);
        __nv_bfloat16 m = __float2bfloat16(r1);
        __nv_bfloat16 l = __float2bfloat16(r1 - __bfloat162float(m));
        size_t o = (size_t)n * K6 + k;
        Bt[o] = h;
        Bt[o + 1024] = m;
        Bt[o + 2048] = h;
        Bt[o + 3072] = l;
        Bt[o + 4096] = h;
        Bt[o + 5120] = m;
    }
}

__global__ __launch_bounds__(256) void transpose_split3(
    const float* __restrict__ W, int ldw, __nv_bfloat16* __restrict__ Bt)
{
    __shared__ float t[32][33];
    int n0 = blockIdx.x * 32, k0 = blockIdx.y * 32;
    int tx = threadIdx.x & 31, ty = threadIdx.x >> 5;
    #pragma unroll
    for (int i = 0; i < 32; i += 8)
        t[ty + i][tx] = W[(size_t)(k0 + ty + i) * ldw + n0 + tx];
    __syncthreads();
    #pragma unroll
    for (int i = 0; i < 32; i += 8) {
        int n = n0 + ty + i, k = k0 + tx;
        float v = t[tx][ty + i];
        __nv_bfloat16 h = __float2bfloat16(v);
        __nv_bfloat16 m = __float2bfloat16(v - __bfloat162float(h));
        size_t o = (size_t)n * KT3 + k;
        Bt[o] = h;
        Bt[o + 1024] = m;
        Bt[o + 2048] = h;
    }
}

// ======================= small pipeline kernels ============================
__global__ void router_pool_kernel()
{
    int blk = blockIdx.x;
    int b = blk / MEXP, m = blk % MEXP;
    int p = m / POOLN, q = m % POOLN;
    int hs = (p * GRID) / POOLN, he = ((p + 1) * GRID + POOLN - 1) / POOLN;
    int ws = (q * GRID) / POOLN, we = ((q + 1) * GRID + POOLN - 1) / POOLN;
    float inv = 1.0f / (float)((he - hs) * (we - ws));
    for (int c = threadIdx.x; c < CDIM; c += blockDim.x) {
        float s = 0.f;
        for (int h = hs; h < he; h++)
            for (int w = ws; w < we; w++)
                s += g_qkv[((size_t)(b * NTOK + h * GRID + w)) * (3 * CDIM) + c];
        g_router[(size_t)blk * CDIM + c] = s * inv;
    }
}

#define LT 64
__global__ __launch_bounds__(256) void logits_kernel()
{
    __shared__ float q_s[LT][65];
    __shared__ float k_s[LT][65];
    __shared__ float r_s[MEXP][65];

    int bh = blockIdx.y;
    int b = bh / HEADS, h = bh % HEADS;
    int n0 = blockIdx.x * LT;
    int tid = threadIdx.x;

    for (int i = tid; i < MEXP * 16; i += 256) {
        int m = i >> 4, c = (i & 15) * 4;
        float4 v = *(const float4*)&g_router[(size_t)(b * MEXP + m) * CDIM + h * HDIM + c];
        r_s[m][c] = v.x; r_s[m][c + 1] = v.y; r_s[m][c + 2] = v.z; r_s[m][c + 3] = v.w;
    }
    #pragma unroll
    for (int it = 0; it < 4; it++) {
        int i = tid + it * 256;
        int row = i >> 4, c = (i & 15) * 4;
        int n = n0 + row;
        float4 qv = make_float4(0.f, 0.f, 0.f, 0.f), kv = qv;
        if (n < NTOK) {
            const float* base = &g_qkv[(size_t)(b * NTOK + n) * (3 * CDIM) + h * HDIM + c];
            qv = *(const float4*)base;
            kv = *(const float4*)(base + CDIM);
        }
        q_s[row][c] = qv.x; q_s[row][c + 1] = qv.y; q_s[row][c + 2] = qv.z; q_s[row][c + 3] = qv.w;
        k_s[row][c] = kv.x; k_s[row][c + 1] = kv.y; k_s[row][c + 2] = kv.z; k_s[row][c + 3] = kv.w;
    }
    __syncthreads();

    const int nl = tid & 63;
    const int g = tid >> 6;
    float acck[7], accq[7];
    #pragma unroll
    for (int j = 0; j < 7; j++) { acck[j] = 0.f; accq[j] = 0.f; }

    for (int d = 0; d < HDIM; d++) {
        float qv = q_s[nl][d];
        float kv = k_s[nl][d];
        #pragma unroll
        for (int j = 0; j < 7; j++) {
            int m = g + 4 * j;
            int mc = (m < MEXP) ? m : 0;
            float r = r_s[mc][d];
            acck[j] += r * kv;
            accq[j] += r * qv;
        }
    }
    int n = n0 + nl;
    if (n < NTOK) {
        #pragma unroll
        for (int j = 0; j < 7; j++) {
            int m = g + 4 * j;
            if (m < MEXP) {
                size_t o = ((size_t)(bh * MEXP + m)) * NTOK + n;
                g_rlog[o] = acck[j];
                g_gate[o] = accq[j];
            }
        }
    }
}

__global__ __launch_bounds__(256) void softmax_topk_kernel()
{
    __shared__ float swv[8];
    __shared__ int   swi[8];
    __shared__ float selv[KSEL];
    __shared__ int   seli[KSEL];
    __shared__ float s_inv;

    int row = blockIdx.x;
    float* r = &g_rlog[(size_t)row * NTOK];
    int tid = threadIdx.x, lane = tid & 31, wid = tid >> 5;

    float vals[5];
    #pragma unroll
    for (int i = 0; i < 5; i++) {
        int n = tid + (i << 8);
        vals[i] = (n < NTOK) ? r[n] : -CUDART_INF_F;
    }

    for (int it = 0; it < KSEL; it++) {
        float bv = -CUDART_INF_F; int bi = 0x7FFFFFFF;
        #pragma unroll
        for (int i = 0; i < 5; i++) {
            int n = tid + (i << 8);
            float v = vals[i];
            if (v > bv || (v == bv && n < bi)) { bv = v; bi = n; }
        }
        #pragma unroll
        for (int off = 16; off > 0; off >>= 1) {
            float ov = __shfl_xor_sync(0xFFFFFFFFu, bv, off);
            int   oi = __shfl_xor_sync(0xFFFFFFFFu, bi, off);
            if (ov > bv || (ov == bv && oi < bi)) { bv = ov; bi = oi; }
        }
        if (lane == 0) { swv[wid] = bv; swi[wid] = bi; }
        __syncthreads();
        if (tid == 0) {
            float gv = swv[0]; int gi = swi[0];
            #pragma unroll
            for (int ww = 1; ww < 8; ww++)
                if (swv[ww] > gv || (swv[ww] == gv && swi[ww] < gi)) { gv = swv[ww]; gi = swi[ww]; }
            selv[it] = gv; seli[it] = gi;
        }
        __syncthreads();
        int sn = seli[it];
        if (tid == (sn & 255)) vals[sn >> 8] = -CUDART_INF_F;
    }

    if (tid < KSEL) g_topk[(size_t)row * KSEL + tid] = seli[tid];
    float mx = selv[0];
    for (int it = 0; it < KSEL; it++) {
        int sn = seli[it];
        if (tid == (sn & 255)) vals[sn >> 8] = selv[it];
    }

    float ev[5];
    float psum = 0.f;
    #pragma unroll
    for (int i = 0; i < 5; i++) {
        int n = tid + (i << 8);
        float e = (n < NTOK) ? __expf((vals[i] - mx) * SCALE) : 0.f;
        ev[i] = e;
        psum += e;
    }
    #pragma unroll
    for (int off = 16; off > 0; off >>= 1)
        psum += __shfl_xor_sync(0xFFFFFFFFu, psum, off);
    if (lane == 0) swv[wid] = psum;
    __syncthreads();
    if (tid == 0) {
        float s = 0.f;
        #pragma unroll
        for (int ww = 0; ww < 8; ww++) s += swv[ww];
        s_inv = 1.0f / s;
    }
    __syncthreads();
    float inv = s_inv;
    #pragma unroll
    for (int i = 0; i < 5; i++) {
        int n = tid + (i << 8);
        if (n < NTOK) r[n] = ev[i] * inv;
    }
}

#define AV_TILES 33
__global__ __launch_bounds__(256) void agent_value_part()
{
    __shared__ float p_s[MEXP][32];
    __shared__ float v_s[32][HDIM];
    int bh = blockIdx.x;
    int ch = blockIdx.y;
    int b = bh / HEADS, h = bh % HEADS;
    int tid = threadIdx.x;
    int tile0 = ch * 9;
    int tile1 = tile0 + 9; if (tile1 > AV_TILES) tile1 = AV_TILES;

    float acc[7];
    #pragma unroll
    for (int i = 0; i < 7; i++) acc[i] = 0.f;

    for (int tile = tile0; tile < tile1; tile++) {
        int t0 = tile * 32;
        for (int e = tid; e < MEXP * 32; e += 256) {
            int m = e / 32, n = e % 32;
            p_s[m][n] = (t0 + n < NTOK)
                ? g_rlog[((size_t)(bh * MEXP + m)) * NTOK + t0 + n] : 0.f;
        }
        for (int e = tid; e < 32 * HDIM; e += 256) {
            int n = e / HDIM, d = e % HDIM;
            v_s[n][d] = (t0 + n < NTOK)
                ? g_qkv[(size_t)(b * NTOK + t0 + n) * (3 * CDIM) + 2 * CDIM + h * HDIM + d]
                : 0.f;
        }
        __syncthreads();
        for (int n = 0; n < 32; n++) {
            #pragma unroll
            for (int i = 0; i < 7; i++) {
                int pidx = tid + 256 * i;
                if (pidx < MEXP * HDIM) {
                    int m = pidx >> 6, d = pidx & 63;
                    acc[i] += p_s[m][n] * v_s[n][d];
                }
            }
        }
        __syncthreads();
    }
    #pragma unroll
    for (int i = 0; i < 7; i++) {
        int pidx = tid + 256 * i;
        if (pidx < MEXP * HDIM)
            g_avpart[ch][(size_t)bh * MEXP * HDIM + pidx] = acc[i];
    }
}

__global__ __launch_bounds__(256) void agent_value_reduce()
{
    int idx = blockIdx.x * 256 + threadIdx.x;
    if (idx < BH * MEXP * HDIM)
        g_agentv[idx] = g_avpart[0][idx] + g_avpart[1][idx]
                      + g_avpart[2][idx] + g_avpart[3][idx];
}

// ======================= expert-grouped attention ==========================
__global__ __launch_bounds__(256) void zero_cnt()
{
    int idx = blockIdx.x * 256 + threadIdx.x;
    if (idx < BH * MEXP) g_cnt[idx] = 0;
}

// E0: per query find argmax expert (strict >, lowest index) and bucket it.
__global__ __launch_bounds__(256) void expert_select()
{
    int bh = blockIdx.y;
    int n = blockIdx.x * 256 + threadIdx.x;
    if (n >= NTOK) return;
    const float* gb = &g_gate[(size_t)bh * MEXP * NTOK + n];
    float best = -CUDART_INF_F; int ei = 0;
    #pragma unroll
    for (int m = 0; m < MEXP; m++) {
        float v = gb[(size_t)m * NTOK];
        if (v > best) { best = v; ei = m; }
    }
    int blk = bh * MEXP + ei;
    int pos = atomicAdd(&g_cnt[blk], 1);
    g_qlist[(size_t)blk * NTOK + pos] = n;
}

// E2: block per (bh, expert). Smem-resident K/V/agent rows; warp-per-query.
__global__ __launch_bounds__(256) void attn_expert()
{
    __shared__ float K_s[HDIM][KSEL + 1];      // transposed: [d][k]
    __shared__ float V_s[KSEL][HDIM];
    __shared__ float ag_s[MEXP][HDIM];
    __shared__ int   keys[KSEL];
    __shared__ float q_s[8][HDIM];
    __shared__ float w_s[8][2 * KSEL];

    int blk = blockIdx.x;
    int nq = g_cnt[blk];
    if (nq == 0) return;

    int bh = blk / MEXP;
    int b = bh / HEADS, h = bh % HEADS;
    int tid = threadIdx.x;
    int warp = tid >> 5, lane = tid & 31;

    if (tid < KSEL) keys[tid] = g_topk[(size_t)blk * KSEL + tid];
    __syncthreads();

    // load K (transposed) and V rows of this expert's 25 keys
    for (int e = tid; e < KSEL * HDIM; e += 256) {
        int k = e >> 6, d = e & 63;
        const float* base = &g_qkv[(size_t)(b * NTOK + keys[k]) * (3 * CDIM) + h * HDIM + d];
        K_s[d][k] = base[CDIM];          // key
        V_s[k][d] = base[2 * CDIM];      // value
    }
    for (int e = tid; e < MEXP * HDIM; e += 256)
        ((float*)ag_s)[e] = g_agentv[(size_t)bh * MEXP * HDIM + e];
    __syncthreads();

    const int* ql = &g_qlist[(size_t)blk * NTOK];
    for (int iq = warp; iq < nq; iq += 8) {
        int n = ql[iq];
        // stage q into smem (warp-private row)
        float2 qp = *(const float2*)
            &g_qkv[(size_t)(b * NTOK + n) * (3 * CDIM) + h * HDIM + 2 * lane];
        q_s[warp][2 * lane] = qp.x;
        q_s[warp][2 * lane + 1] = qp.y;
        __syncwarp();

        // lane<25: gate logit (gather) + moba logit (smem dot)
        float gv = -CUDART_INF_F, mv = -CUDART_INF_F;
        if (lane < KSEL) {
            gv = g_gate[((size_t)bh * MEXP + lane) * NTOK + n] * SCALE;
            float acc = 0.f;
            #pragma unroll
            for (int d = 0; d < HDIM; d++)
                acc += q_s[warp][d] * K_s[d][lane];
            mv = acc * SCALE;
        }
        // warp softmax over 50 logits
        float mx = fmaxf(gv, mv);
        #pragma unroll
        for (int off = 16; off > 0; off >>= 1)
            mx = fmaxf(mx, __shfl_xor_sync(0xFFFFFFFFu, mx, off));
        float eg = (lane < KSEL) ? __expf(gv - mx) : 0.f;
        float em = (lane < KSEL) ? __expf(mv - mx) : 0.f;
        float s = eg + em;
        #pragma unroll
        for (int off = 16; off > 0; off >>= 1)
            s += __shfl_xor_sync(0xFFFFFFFFu, s, off);
        float inv = 1.0f / s;
        if (lane < KSEL) {
            w_s[warp][lane] = eg * inv;
            w_s[warp][KSEL + lane] = em * inv;
        }
        __syncwarp();

        // output: lane covers d = 2*lane, 2*lane+1
        float o0 = 0.f, o1 = 0.f;
        #pragma unroll
        for (int j = 0; j < KSEL; j++) {
            float wa = w_s[warp][j];
            float wm = w_s[warp][KSEL + j];
            float2 av = *(const float2*)&ag_s[j][2 * lane];
            float2 vv = *(const float2*)&V_s[j][2 * lane];
            o0 += wa * av.x + wm * vv.x;
            o1 += wa * av.y + wm * vv.y;
        }
        // write A'3 = [h|h|m] bf16 (GEMM2 input)
        __nv_bfloat16 h0 = __float2bfloat16(o0);
        __nv_bfloat16 m0 = __float2bfloat16(o0 - __bfloat162float(h0));
        __nv_bfloat16 h1 = __float2bfloat16(o1);
        __nv_bfloat16 m1 = __float2bfloat16(o1 - __bfloat162float(h1));
        size_t o3 = (size_t)(b * NTOK + n) * KT3 + h * HDIM + 2 * lane;
        __nv_bfloat162 ph; ph.x = h0; ph.y = h1;
        __nv_bfloat162 pm; pm.x = m0; pm.y = m1;
        *(__nv_bfloat162*)&g_a3[o3] = ph;
        *(__nv_bfloat162*)&g_a3[o3 + 1024] = ph;
        *(__nv_bfloat162*)&g_a3[o3 + 2048] = pm;
        __syncwarp();
    }
}

// ---------------------------------------------------------------------------
extern "C" void kernel_launch(void* const* d_in, const int* in_sizes, int n_in,
                              void* d_out, int out_size)
{
    const float* x     = (const float*)d_in[0];
    const float* Wqkv  = (const float*)d_in[1];
    const float* Wproj = (const float*)d_in[2];
    const float* bproj = (const float*)d_in[3];
    float* out = (float*)d_out;

    __nv_bfloat16* a6;   cudaGetSymbolAddress((void**)&a6,   g_a6);
    __nv_bfloat16* a3;   cudaGetSymbolAddress((void**)&a3,   g_a3);
    __nv_bfloat16* b6qk; cudaGetSymbolAddress((void**)&b6qk, g_b6qk);
    __nv_bfloat16* b3v;  cudaGetSymbolAddress((void**)&b3v,  g_b3v);
    __nv_bfloat16* b3p;  cudaGetSymbolAddress((void**)&b3p,  g_b3p);

    cudaFuncSetAttribute(tc_gemm,  cudaFuncAttributeMaxDynamicSharedMemorySize, DYN_SMEM);
    cudaFuncSetAttribute(gemm_qkv, cudaFuncAttributeMaxDynamicSharedMemorySize, DYN_SMEM);

    // --- conversions for GEMM1 ---
    split63_rows<<<(MROWS * CDIM + 255) / 256, 256>>>(x, a6, a3, MROWS * CDIM);
    {
        dim3 g(2 * CDIM / 32, CDIM / 32);
        transpose_split6<<<g, 256>>>(Wqkv, 3 * CDIM, b6qk);
    }
    {
        dim3 g(CDIM / 32, CDIM / 32);
        transpose_split3<<<g, 256>>>(Wqkv + 2 * CDIM, 3 * CDIM, b3v);
    }
    // --- GEMM1 (q,k bf16x6 + v bf16x3, one merged launch) ---
    {
        dim3 grid(24, (MROWS + BM - 1) / BM);
        gemm_qkv<<<grid, 256, DYN_SMEM>>>();
    }
    router_pool_kernel<<<BATCH * MEXP, 256>>>();
    {
        dim3 grid((NTOK + LT - 1) / LT, BH);
        logits_kernel<<<grid, 256>>>();
    }
    softmax_topk_kernel<<<BH * MEXP, 256>>>();
    {
        dim3 grid(BH, 4);
        agent_value_part<<<grid, 256>>>();
    }
    agent_value_reduce<<<(BH * MEXP * HDIM + 255) / 256, 256>>>();
    // --- expert-grouped mixed attention ---
    zero_cnt<<<(BH * MEXP + 255) / 256, 256>>>();
    {
        dim3 grid((NTOK + 255) / 256, BH);
        expert_select<<<grid, 256>>>();
    }
    attn_expert<<<BH * MEXP, 256>>>();            // writes A'3
    // --- GEMM2: out = attn @ Wproj + b (bf16x3) ---
    {
        dim3 g(CDIM / 32, CDIM / 32);
        transpose_split3<<<g, 256>>>(Wproj, CDIM, b3p);
    }
    {
        dim3 grid(CDIM / BN, (MROWS + BM - 1) / BM);
        tc_gemm<<<grid, 256, DYN_SMEM>>>(a3, KT3, b3p, KT3, bproj,
                                         out, CDIM, MROWS, KT3 / BKE);
    }
}

// round 14
// speedup vs baseline: 1.9111x; 1.0285x over previous
#include <cuda_runtime.h>
#include <cuda_bf16.h>
#include <math_constants.h>
#include <cstdint>

// ---------------------------------------------------------------------------
// MiTA Attention. compute_103 PTX target (no tcgen05) -> mma.sync HMMA bf16.
// q/k via bf16x6 split (err ~1e-7, decision-safe); v & proj via bf16x3.
// Round 13: dedup split storage ([h|m|l] physical + 2-bit k-block remap in
// GEMM), expert-argmax fused into logits.
// ---------------------------------------------------------------------------

#define BATCH 8
#define NTOK 1025
#define CDIM 1024
#define HEADS 16
#define HDIM 64
#define MEXP 25
#define KSEL 25
#define GRID 32
#define POOLN 5
#define SCALE 0.125f
#define MROWS (BATCH * NTOK)       // 8200
#define BH (BATCH * HEADS)         // 128
#define K6 (6 * CDIM)              // 6144 (logical)
#define KT3 (3 * CDIM)             // 3072 (logical)

// ---------------- scratch ----------------
__device__ float g_qkv[BATCH * NTOK * 3 * CDIM];
__device__ float g_router[BATCH * MEXP * CDIM];
__device__ float g_rlog[BH * MEXP * NTOK];
__device__ float g_gate[BH * MEXP * NTOK];        // layout [bh][m][n]
__device__ int   g_topk[BH * MEXP * KSEL];
__device__ float g_agentv[BH * MEXP * HDIM];
__device__ float g_avpart[4][BH * MEXP * HDIM];
__device__ int   g_cnt[BH * MEXP];
__device__ int   g_qlist[BH * MEXP * NTOK];
__device__ __nv_bfloat16 g_ax[MROWS * 3 * CDIM];   // x splits [h|m|l] (50 MB)
__device__ __nv_bfloat16 g_aat[MROWS * 2 * CDIM];  // attn splits [h|m]
__device__ __nv_bfloat16 g_bqk[2 * CDIM * 3 * CDIM]; // Wqkv q,k cols [h|m|l]
__device__ __nv_bfloat16 g_bv[CDIM * 2 * CDIM];      // Wqkv v cols [h|m]
__device__ __nv_bfloat16 g_bp[CDIM * 2 * CDIM];      // Wproj [h|m]

// k-block maps (2 bits per logical 1024-block)
#define AMAP6 0x520u   // [h,h,l,h,m,m] -> 0,0,2,0,1,1
#define BMAP6 0x484u   // [h,m,h,l,h,m] -> 0,1,0,2,0,1
#define AMAP3 0x10u    // [h,h,m] -> 0,0,1
#define BMAP3 0x4u     // [h,m,h] -> 0,1,0

// ======================= helpers ===========================================
__device__ __forceinline__ uint32_t smem_u32(const void* p) {
    uint32_t a;
    asm("{ .reg .u64 t; cvta.to.shared.u64 t, %1; cvt.u32.u64 %0, t; }" : "=r"(a) : "l"(p));
    return a;
}
#define CP16(dst, src, nbytes) \
    asm volatile("cp.async.cg.shared.global [%0], [%1], 16, %2;" \
        :: "r"(dst), "l"(src), "r"(nbytes) : "memory")

__device__ __forceinline__ void ldmx4(uint32_t& r0, uint32_t& r1, uint32_t& r2,
                                      uint32_t& r3, uint32_t addr) {
    asm volatile("ldmatrix.sync.aligned.m8n8.x4.shared.b16 {%0,%1,%2,%3}, [%4];"
        : "=r"(r0), "=r"(r1), "=r"(r2), "=r"(r3) : "r"(addr));
}
__device__ __forceinline__ void mma16816(float* c, const uint32_t* a,
                                         uint32_t b0, uint32_t b1) {
    asm volatile(
        "mma.sync.aligned.m16n8k16.row.col.f32.bf16.bf16.f32 "
        "{%0,%1,%2,%3}, {%4,%5,%6,%7}, {%8,%9}, {%0,%1,%2,%3};"
        : "+f"(c[0]), "+f"(c[1]), "+f"(c[2]), "+f"(c[3])
        : "r"(a[0]), "r"(a[1]), "r"(a[2]), "r"(a[3]), "r"(b0), "r"(b1));
}

// ======================= HMMA GEMM body ====================================
#define BM 128
#define BN 128
#define BKE 64
#define STAGES 3
#define TILE_BYTES (128 * 128)
#define SM_A 0
#define SM_B (STAGES * TILE_BYTES)
#define DYN_SMEM (2 * STAGES * TILE_BYTES + 1024)

__device__ __forceinline__ void load_tile(
    const __nv_bfloat16* __restrict__ A, int ldaP, uint32_t aMap,
    const __nv_bfloat16* __restrict__ Bt, int ldbP, uint32_t bMap,
    int Mrows, int rowBase, int colBase, int kt, int buf, uint32_t sb, int tid)
{
    const int k0 = kt * BKE;
    const int kblk = k0 >> 10, koff = k0 & 1023;
    const int aoff = (int)((aMap >> (2 * kblk)) & 3u) * 1024 + koff;
    const int boff = (int)((bMap >> (2 * kblk)) & 3u) * 1024 + koff;
    #pragma unroll
    for (int j = 0; j < 4; j++) {
        int i = tid + 256 * j;
        int r = i >> 3, c = i & 7;
        uint32_t dst = sb + SM_A + buf * TILE_BYTES
                     + r * 128 + ((c * 16) ^ ((r & 7) * 16));
        bool ok = (rowBase + r) < Mrows;
        const __nv_bfloat16* src = ok ? (A + (size_t)(rowBase + r) * ldaP + aoff + c * 8) : A;
        CP16(dst, src, ok ? 16 : 0);
    }
    #pragma unroll
    for (int j = 0; j < 4; j++) {
        int i = tid + 256 * j;
        int r = i >> 3, c = i & 7;
        uint32_t dst = sb + SM_B + buf * TILE_BYTES
                     + r * 128 + ((c * 16) ^ ((r & 7) * 16));
        const __nv_bfloat16* src = Bt + (size_t)(colBase + r) * ldbP + boff + c * 8;
        CP16(dst, src, 16);
    }
    asm volatile("cp.async.commit_group;" ::: "memory");
}

__device__ __forceinline__ void gemm_body(
    const __nv_bfloat16* __restrict__ A, int ldaP, uint32_t aMap,
    const __nv_bfloat16* __restrict__ Bt, int ldbP, uint32_t bMap,
    const float* __restrict__ bias, float* __restrict__ C, int ldc,
    int Mrows, int nkt, int rowBase, int colBase, uint32_t sb, int tid)
{
    const int lane = tid & 31, w = tid >> 5;
    const int wm = w >> 1, wn = w & 1;

    const uint32_t xm = (lane & 7) * 16;
    uint32_t aRow[2];
    #pragma unroll
    for (int mi = 0; mi < 2; mi++)
        aRow[mi] = (uint32_t)(wm * 32 + mi * 16 + (lane & 15)) * 128u;
    const uint32_t aCol = 16u * (lane >> 4);
    uint32_t bRow[4];
    #pragma unroll
    for (int p = 0; p < 4; p++)
        bRow[p] = (uint32_t)(wn * 64 + p * 16 + (lane & 7) + 8 * (lane >> 4)) * 128u;
    const uint32_t bCol = 16u * ((lane >> 3) & 1);

    float acc[2][8][4];
    #pragma unroll
    for (int mi = 0; mi < 2; mi++)
        #pragma unroll
        for (int ni = 0; ni < 8; ni++)
            #pragma unroll
            for (int r = 0; r < 4; r++) acc[mi][ni][r] = 0.f;

    load_tile(A, ldaP, aMap, Bt, ldbP, bMap, Mrows, rowBase, colBase, 0, 0, sb, tid);
    load_tile(A, ldaP, aMap, Bt, ldbP, bMap, Mrows, rowBase, colBase, 1, 1, sb, tid);

    for (int kt = 0; kt < nkt; kt++) {
        if (kt == nkt - 1) asm volatile("cp.async.wait_group 0;" ::: "memory");
        else               asm volatile("cp.async.wait_group 1;" ::: "memory");
        __syncthreads();

        if (kt + 2 < nkt)
            load_tile(A, ldaP, aMap, Bt, ldbP, bMap, Mrows, rowBase, colBase,
                      kt + 2, (kt + 2) % STAGES, sb, tid);

        const int buf = kt % STAGES;
        const uint32_t baseA = sb + SM_A + buf * TILE_BYTES;
        const uint32_t baseB = sb + SM_B + buf * TILE_BYTES;
        #pragma unroll
        for (int kf = 0; kf < 4; kf++) {
            const uint32_t kb = kf * 32;
            uint32_t af[2][4], bf[8][2];
            #pragma unroll
            for (int mi = 0; mi < 2; mi++)
                ldmx4(af[mi][0], af[mi][1], af[mi][2], af[mi][3],
                      baseA + aRow[mi] + ((kb + aCol) ^ xm));
            #pragma unroll
            for (int p = 0; p < 4; p++)
                ldmx4(bf[2 * p][0], bf[2 * p][1], bf[2 * p + 1][0], bf[2 * p + 1][1],
                      baseB + bRow[p] + ((kb + bCol) ^ xm));
            #pragma unroll
            for (int mi = 0; mi < 2; mi++)
                #pragma unroll
                for (int ni = 0; ni < 8; ni++)
                    mma16816(acc[mi][ni], af[mi], bf[ni][0], bf[ni][1]);
        }
    }

    const int colW = colBase + wn * 64 + 2 * (lane & 3);
    #pragma unroll
    for (int mi = 0; mi < 2; mi++) {
        int r0 = rowBase + wm * 32 + mi * 16 + (lane >> 2);
        #pragma unroll
        for (int ni = 0; ni < 8; ni++) {
            int col = colW + ni * 8;
            float bx = 0.f, by = 0.f;
            if (bias) { bx = bias[col]; by = bias[col + 1]; }
            if (r0 < Mrows)
                *(float2*)&C[(size_t)r0 * ldc + col] =
                    make_float2(acc[mi][ni][0] + bx, acc[mi][ni][1] + by);
            if (r0 + 8 < Mrows)
                *(float2*)&C[(size_t)(r0 + 8) * ldc + col] =
                    make_float2(acc[mi][ni][2] + bx, acc[mi][ni][3] + by);
        }
    }
}

// Merged GEMM1a (q,k bf16x6) + GEMM1b (v bf16x3).
__global__ __launch_bounds__(256, 2) void gemm_qkv()
{
    extern __shared__ char dsm[];
    uint32_t sb = (smem_u32(dsm) + 1023u) & ~1023u;
    const int tid = threadIdx.x;
    const int rowBase = blockIdx.y * BM;
    if (blockIdx.x < 16) {
        gemm_body(g_ax, 3 * CDIM, AMAP6, g_bqk, 3 * CDIM, BMAP6,
                  nullptr, g_qkv, 3 * CDIM,
                  MROWS, K6 / BKE, rowBase, blockIdx.x * BN, sb, tid);
    } else {
        gemm_body(g_ax, 3 * CDIM, AMAP3, g_bv, 2 * CDIM, BMAP3,
                  nullptr, g_qkv + 2 * CDIM, 3 * CDIM,
                  MROWS, KT3 / BKE, rowBase, (blockIdx.x - 16) * BN, sb, tid);
    }
}

// GEMM2: out = attn @ Wproj + b.
__global__ __launch_bounds__(256, 2) void gemm_out(const float* bias, float* C)
{
    extern __shared__ char dsm[];
    uint32_t sb = (smem_u32(dsm) + 1023u) & ~1023u;
    gemm_body(g_aat, 2 * CDIM, AMAP3, g_bp, 2 * CDIM, BMAP3,
              bias, C, CDIM, MROWS, KT3 / BKE,
              blockIdx.y * BM, blockIdx.x * BN, sb, threadIdx.x);
}

// ======================= split / transpose conversions =====================
// x -> [h|m|l] (one pass; serves GEMM1a and GEMM1b)
__global__ __launch_bounds__(256) void split_hml(
    const float* __restrict__ src, __nv_bfloat16* __restrict__ dst, int total)
{
    int idx = blockIdx.x * 256 + threadIdx.x;
    if (idx >= total) return;
    int r = idx >> 10, k = idx & 1023;
    float v = src[idx];
    __nv_bfloat16 h = __float2bfloat16(v);
    float r1 = v - __bfloat162float(h);
    __nv_bfloat16 m = __float2bfloat16(r1);
    __nv_bfloat16 l = __float2bfloat16(r1 - __bfloat162float(m));
    size_t o = (size_t)r * (3 * CDIM) + k;
    dst[o] = h;
    dst[o + 1024] = m;
    dst[o + 2048] = l;
}

// W col slice (transposed) -> [h|m|l], ld 3072
__global__ __launch_bounds__(256) void transpose_hml(
    const float* __restrict__ W, int ldw, __nv_bfloat16* __restrict__ Bt)
{
    __shared__ float t[32][33];
    int n0 = blockIdx.x * 32, k0 = blockIdx.y * 32;
    int tx = threadIdx.x & 31, ty = threadIdx.x >> 5;
    #pragma unroll
    for (int i = 0; i < 32; i += 8)
        t[ty + i][tx] = W[(size_t)(k0 + ty + i) * ldw + n0 + tx];
    __syncthreads();
    #pragma unroll
    for (int i = 0; i < 32; i += 8) {
        int n = n0 + ty + i, k = k0 + tx;
        float v = t[tx][ty + i];
        __nv_bfloat16 h = __float2bfloat16(v);
        float r1 = v - __bfloat162float(h);
        __nv_bfloat16 m = __float2bfloat16(r1);
        __nv_bfloat16 l = __float2bfloat16(r1 - __bfloat162float(m));
        size_t o = (size_t)n * (3 * CDIM) + k;
        Bt[o] = h;
        Bt[o + 1024] = m;
        Bt[o + 2048] = l;
    }
}

// W col slice (transposed) -> [h|m], ld 2048
__global__ __launch_bounds__(256) void transpose_hm(
    const float* __restrict__ W, int ldw, __nv_bfloat16* __restrict__ Bt)
{
    __shared__ float t[32][33];
    int n0 = blockIdx.x * 32, k0 = blockIdx.y * 32;
    int tx = threadIdx.x & 31, ty = threadIdx.x >> 5;
    #pragma unroll
    for (int i = 0; i < 32; i += 8)
        t[ty + i][tx] = W[(size_t)(k0 + ty + i) * ldw + n0 + tx];
    __syncthreads();
    #pragma unroll
    for (int i = 0; i < 32; i += 8) {
        int n = n0 + ty + i, k = k0 + tx;
        float v = t[tx][ty + i];
        __nv_bfloat16 h = __float2bfloat16(v);
        __nv_bfloat16 m = __float2bfloat16(v - __bfloat162float(h));
        size_t o = (size_t)n * (2 * CDIM) + k;
        Bt[o] = h;
        Bt[o + 1024] = m;
    }
}

// ======================= small pipeline kernels ============================
__global__ void router_pool_kernel()
{
    int blk = blockIdx.x;
    int b = blk / MEXP, m = blk % MEXP;
    int p = m / POOLN, q = m % POOLN;
    int hs = (p * GRID) / POOLN, he = ((p + 1) * GRID + POOLN - 1) / POOLN;
    int ws = (q * GRID) / POOLN, we = ((q + 1) * GRID + POOLN - 1) / POOLN;
    float inv = 1.0f / (float)((he - hs) * (we - ws));
    for (int c = threadIdx.x; c < CDIM; c += blockDim.x) {
        float s = 0.f;
        for (int h = hs; h < he; h++)
            for (int w = ws; w < we; w++)
                s += g_qkv[((size_t)(b * NTOK + h * GRID + w)) * (3 * CDIM) + c];
        g_router[(size_t)blk * CDIM + c] = s * inv;
    }
}

__global__ __launch_bounds__(256) void zero_cnt()
{
    int idx = blockIdx.x * 256 + threadIdx.x;
    if (idx < BH * MEXP) g_cnt[idx] = 0;
}

// logits + fused per-query expert argmax & bucketing.
#define LT 64
__global__ __launch_bounds__(256) void logits_kernel()
{
    __shared__ float q_s[LT][65];
    __shared__ float k_s[LT][65];
    __shared__ float r_s[MEXP][65];
    __shared__ float gq[LT][28];     // per-token gate logits (for argmax)

    int bh = blockIdx.y;
    int b = bh / HEADS, h = bh % HEADS;
    int n0 = blockIdx.x * LT;
    int tid = threadIdx.x;

    for (int i = tid; i < MEXP * 16; i += 256) {
        int m = i >> 4, c = (i & 15) * 4;
        float4 v = *(const float4*)&g_router[(size_t)(b * MEXP + m) * CDIM + h * HDIM + c];
        r_s[m][c] = v.x; r_s[m][c + 1] = v.y; r_s[m][c + 2] = v.z; r_s[m][c + 3] = v.w;
    }
    #pragma unroll
    for (int it = 0; it < 4; it++) {
        int i = tid + it * 256;
        int row = i >> 4, c = (i & 15) * 4;
        int n = n0 + row;
        float4 qv = make_float4(0.f, 0.f, 0.f, 0.f), kv = qv;
        if (n < NTOK) {
            const float* base = &g_qkv[(size_t)(b * NTOK + n) * (3 * CDIM) + h * HDIM + c];
            qv = *(const float4*)base;
            kv = *(const float4*)(base + CDIM);
        }
        q_s[row][c] = qv.x; q_s[row][c + 1] = qv.y; q_s[row][c + 2] = qv.z; q_s[row][c + 3] = qv.w;
        k_s[row][c] = kv.x; k_s[row][c + 1] = kv.y; k_s[row][c + 2] = kv.z; k_s[row][c + 3] = kv.w;
    }
    __syncthreads();

    const int nl = tid & 63;
    const int g = tid >> 6;
    float acck[7], accq[7];
    #pragma unroll
    for (int j = 0; j < 7; j++) { acck[j] = 0.f; accq[j] = 0.f; }

    for (int d = 0; d < HDIM; d++) {
        float qv = q_s[nl][d];
        float kv = k_s[nl][d];
        #pragma unroll
        for (int j = 0; j < 7; j++) {
            int m = g + 4 * j;
            int mc = (m < MEXP) ? m : 0;
            float r = r_s[mc][d];
            acck[j] += r * kv;
            accq[j] += r * qv;
        }
    }
    int n = n0 + nl;
    if (n < NTOK) {
        #pragma unroll
        for (int j = 0; j < 7; j++) {
            int m = g + 4 * j;
            if (m < MEXP) {
                size_t o = ((size_t)(bh * MEXP + m)) * NTOK + n;
                g_rlog[o] = acck[j];
                g_gate[o] = accq[j];
                gq[nl][m] = accq[j];
            }
        }
    }
    __syncthreads();

    // fused expert argmax (strict >, lowest index wins) + bucket
    if (tid < LT) {
        int n2 = n0 + tid;
        if (n2 < NTOK) {
            float best = -CUDART_INF_F; int ei = 0;
            #pragma unroll
            for (int m = 0; m < MEXP; m++) {
                float v = gq[tid][m];
                if (v > best) { best = v; ei = m; }
            }
            int blk = bh * MEXP + ei;
            int pos = atomicAdd(&g_cnt[blk], 1);
            g_qlist[(size_t)blk * NTOK + pos] = n2;
        }
    }
}

__global__ __launch_bounds__(256) void softmax_topk_kernel()
{
    __shared__ float swv[8];
    __shared__ int   swi[8];
    __shared__ float selv[KSEL];
    __shared__ int   seli[KSEL];
    __shared__ float s_inv;

    int row = blockIdx.x;
    float* r = &g_rlog[(size_t)row * NTOK];
    int tid = threadIdx.x, lane = tid & 31, wid = tid >> 5;

    float vals[5];
    #pragma unroll
    for (int i = 0; i < 5; i++) {
        int n = tid + (i << 8);
        vals[i] = (n < NTOK) ? r[n] : -CUDART_INF_F;
    }

    for (int it = 0; it < KSEL; it++) {
        float bv = -CUDART_INF_F; int bi = 0x7FFFFFFF;
        #pragma unroll
        for (int i = 0; i < 5; i++) {
            int n = tid + (i << 8);
            float v = vals[i];
            if (v > bv || (v == bv && n < bi)) { bv = v; bi = n; }
        }
        #pragma unroll
        for (int off = 16; off > 0; off >>= 1) {
            float ov = __shfl_xor_sync(0xFFFFFFFFu, bv, off);
            int   oi = __shfl_xor_sync(0xFFFFFFFFu, bi, off);
            if (ov > bv || (ov == bv && oi < bi)) { bv = ov; bi = oi; }
        }
        if (lane == 0) { swv[wid] = bv; swi[wid] = bi; }
        __syncthreads();
        if (tid == 0) {
            float gv = swv[0]; int gi = swi[0];
            #pragma unroll
            for (int ww = 1; ww < 8; ww++)
                if (swv[ww] > gv || (swv[ww] == gv && swi[ww] < gi)) { gv = swv[ww]; gi = swi[ww]; }
            selv[it] = gv; seli[it] = gi;
        }
        __syncthreads();
        int sn = seli[it];
        if (tid == (sn & 255)) vals[sn >> 8] = -CUDART_INF_F;
    }

    if (tid < KSEL) g_topk[(size_t)row * KSEL + tid] = seli[tid];
    float mx = selv[0];
    for (int it = 0; it < KSEL; it++) {
        int sn = seli[it];
        if (tid == (sn & 255)) vals[sn >> 8] = selv[it];
    }

    float ev[5];
    float psum = 0.f;
    #pragma unroll
    for (int i = 0; i < 5; i++) {
        int n = tid + (i << 8);
        float e = (n < NTOK) ? __expf((vals[i] - mx) * SCALE) : 0.f;
        ev[i] = e;
        psum += e;
    }
    #pragma unroll
    for (int off = 16; off > 0; off >>= 1)
        psum += __shfl_xor_sync(0xFFFFFFFFu, psum, off);
    if (lane == 0) swv[wid] = psum;
    __syncthreads();
    if (tid == 0) {
        float s = 0.f;
        #pragma unroll
        for (int ww = 0; ww < 8; ww++) s += swv[ww];
        s_inv = 1.0f / s;
    }
    __syncthreads();
    float inv = s_inv;
    #pragma unroll
    for (int i = 0; i < 5; i++) {
        int n = tid + (i << 8);
        if (n < NTOK) r[n] = ev[i] * inv;
    }
}

#define AV_TILES 33
__global__ __launch_bounds__(256) void agent_value_part()
{
    __shared__ float p_s[MEXP][32];
    __shared__ float v_s[32][HDIM];
    int bh = blockIdx.x;
    int ch = blockIdx.y;
    int b = bh / HEADS, h = bh % HEADS;
    int tid = threadIdx.x;
    int tile0 = ch * 9;
    int tile1 = tile0 + 9; if (tile1 > AV_TILES) tile1 = AV_TILES;

    float acc[7];
    #pragma unroll
    for (int i = 0; i < 7; i++) acc[i] = 0.f;

    for (int tile = tile0; tile < tile1; tile++) {
        int t0 = tile * 32;
        for (int e = tid; e < MEXP * 32; e += 256) {
            int m = e / 32, n = e % 32;
            p_s[m][n] = (t0 + n < NTOK)
                ? g_rlog[((size_t)(bh * MEXP + m)) * NTOK + t0 + n] : 0.f;
        }
        for (int e = tid; e < 32 * HDIM; e += 256) {
            int n = e / HDIM, d = e % HDIM;
            v_s[n][d] = (t0 + n < NTOK)
                ? g_qkv[(size_t)(b * NTOK + t0 + n) * (3 * CDIM) + 2 * CDIM + h * HDIM + d]
                : 0.f;
        }
        __syncthreads();
        for (int n = 0; n < 32; n++) {
            #pragma unroll
            for (int i = 0; i < 7; i++) {
                int pidx = tid + 256 * i;
                if (pidx < MEXP * HDIM) {
                    int m = pidx >> 6, d = pidx & 63;
                    acc[i] += p_s[m][n] * v_s[n][d];
                }
            }
        }
        __syncthreads();
    }
    #pragma unroll
    for (int i = 0; i < 7; i++) {
        int pidx = tid + 256 * i;
        if (pidx < MEXP * HDIM)
            g_avpart[ch][(size_t)bh * MEXP * HDIM + pidx] = acc[i];
    }
}

__global__ __launch_bounds__(256) void agent_value_reduce()
{
    int idx = blockIdx.x * 256 + threadIdx.x;
    if (idx < BH * MEXP * HDIM)
        g_agentv[idx] = g_avpart[0][idx] + g_avpart[1][idx]
                      + g_avpart[2][idx] + g_avpart[3][idx];
}

// ======================= expert-grouped attention ==========================
__global__ __launch_bounds__(256) void attn_expert()
{
    __shared__ float K_s[HDIM][KSEL + 1];
    __shared__ float V_s[KSEL][HDIM];
    __shared__ float ag_s[MEXP][HDIM];
    __shared__ int   keys[KSEL];
    __shared__ float q_s[8][HDIM];
    __shared__ float w_s[8][2 * KSEL];

    int blk = blockIdx.x;
    int nq = g_cnt[blk];
    if (nq == 0) return;

    int bh = blk / MEXP;
    int b = bh / HEADS, h = bh % HEADS;
    int tid = threadIdx.x;
    int warp = tid >> 5, lane = tid & 31;

    if (tid < KSEL) keys[tid] = g_topk[(size_t)blk * KSEL + tid];
    __syncthreads();

    for (int e = tid; e < KSEL * HDIM; e += 256) {
        int k = e >> 6, d = e & 63;
        const float* base = &g_qkv[(size_t)(b * NTOK + keys[k]) * (3 * CDIM) + h * HDIM + d];
        K_s[d][k] = base[CDIM];
        V_s[k][d] = base[2 * CDIM];
    }
    for (int e = tid; e < MEXP * HDIM; e += 256)
        ((float*)ag_s)[e] = g_agentv[(size_t)bh * MEXP * HDIM + e];
    __syncthreads();

    const int* ql = &g_qlist[(size_t)blk * NTOK];
    for (int iq = warp; iq < nq; iq += 8) {
        int n = ql[iq];
        float2 qp = *(const float2*)
            &g_qkv[(size_t)(b * NTOK + n) * (3 * CDIM) + h * HDIM + 2 * lane];
        q_s[warp][2 * lane] = qp.x;
        q_s[warp][2 * lane + 1] = qp.y;
        __syncwarp();

        float gv = -CUDART_INF_F, mv = -CUDART_INF_F;
        if (lane < KSEL) {
            gv = g_gate[((size_t)bh * MEXP + lane) * NTOK + n] * SCALE;
            float acc = 0.f;
            #pragma unroll
            for (int d = 0; d < HDIM; d++)
                acc += q_s[warp][d] * K_s[d][lane];
            mv = acc * SCALE;
        }
        float mx = fmaxf(gv, mv);
        #pragma unroll
        for (int off = 16; off > 0; off >>= 1)
            mx = fmaxf(mx, __shfl_xor_sync(0xFFFFFFFFu, mx, off));
        float eg = (lane < KSEL) ? __expf(gv - mx) : 0.f;
        float em = (lane < KSEL) ? __expf(mv - mx) : 0.f;
        float s = eg + em;
        #pragma unroll
        for (int off = 16; off > 0; off >>= 1)
            s += __shfl_xor_sync(0xFFFFFFFFu, s, off);
        float inv = 1.0f / s;
        if (lane < KSEL) {
            w_s[warp][lane] = eg * inv;
            w_s[warp][KSEL + lane] = em * inv;
        }
        __syncwarp();

        float o0 = 0.f, o1 = 0.f;
        #pragma unroll
        for (int j = 0; j < KSEL; j++) {
            float wa = w_s[warp][j];
            float wm = w_s[warp][KSEL + j];
            float2 av = *(const float2*)&ag_s[j][2 * lane];
            float2 vv = *(const float2*)&V_s[j][2 * lane];
            o0 += wa * av.x + wm * vv.x;
            o1 += wa * av.y + wm * vv.y;
        }
        // write A' = [h|m] bf16 (GEMM2 maps [h,h,m])
        __nv_bfloat16 h0 = __float2bfloat16(o0);
        __nv_bfloat16 m0 = __float2bfloat16(o0 - __bfloat162float(h0));
        __nv_bfloat16 h1 = __float2bfloat16(o1);
        __nv_bfloat16 m1 = __float2bfloat16(o1 - __bfloat162float(h1));
        size_t oo = (size_t)(b * NTOK + n) * (2 * CDIM) + h * HDIM + 2 * lane;
        __nv_bfloat162 ph; ph.x = h0; ph.y = h1;
        __nv_bfloat162 pm; pm.x = m0; pm.y = m1;
        *(__nv_bfloat162*)&g_aat[oo] = ph;
        *(__nv_bfloat162*)&g_aat[oo + 1024] = pm;
        __syncwarp();
    }
}

// ---------------------------------------------------------------------------
extern "C" void kernel_launch(void* const* d_in, const int* in_sizes, int n_in,
                              void* d_out, int out_size)
{
    const float* x     = (const float*)d_in[0];
    const float* Wqkv  = (const float*)d_in[1];
    const float* Wproj = (const float*)d_in[2];
    const float* bproj = (const float*)d_in[3];
    float* out = (float*)d_out;

    __nv_bfloat16* ax;  cudaGetSymbolAddress((void**)&ax,  g_ax);
    __nv_bfloat16* bqk; cudaGetSymbolAddress((void**)&bqk, g_bqk);
    __nv_bfloat16* bv;  cudaGetSymbolAddress((void**)&bv,  g_bv);
    __nv_bfloat16* bp;  cudaGetSymbolAddress((void**)&bp,  g_bp);

    cudaFuncSetAttribute(gemm_qkv, cudaFuncAttributeMaxDynamicSharedMemorySize, DYN_SMEM);
    cudaFuncSetAttribute(gemm_out, cudaFuncAttributeMaxDynamicSharedMemorySize, DYN_SMEM);

    // --- conversions ---
    split_hml<<<(MROWS * CDIM + 255) / 256, 256>>>(x, ax, MROWS * CDIM);
    {
        dim3 g(2 * CDIM / 32, CDIM / 32);
        transpose_hml<<<g, 256>>>(Wqkv, 3 * CDIM, bqk);           // q,k columns
    }
    {
        dim3 g(CDIM / 32, CDIM / 32);
        transpose_hm<<<g, 256>>>(Wqkv + 2 * CDIM, 3 * CDIM, bv);  // v columns
        transpose_hm<<<g, 256>>>(Wproj, CDIM, bp);                // proj (early)
    }
    // --- GEMM1 ---
    {
        dim3 grid(24, (MROWS + BM - 1) / BM);
        gemm_qkv<<<grid, 256, DYN_SMEM>>>();
    }
    router_pool_kernel<<<BATCH * MEXP, 256>>>();
    zero_cnt<<<(BH * MEXP + 255) / 256, 256>>>();
    {
        dim3 grid((NTOK + LT - 1) / LT, BH);
        logits_kernel<<<grid, 256>>>();                           // + expert bucketing
    }
    softmax_topk_kernel<<<BH * MEXP, 256>>>();
    {
        dim3 grid(BH, 4);
        agent_value_part<<<grid, 256>>>();
    }
    agent_value_reduce<<<(BH * MEXP * HDIM + 255) / 256, 256>>>();
    attn_expert<<<BH * MEXP, 256>>>();                            // writes g_aat [h|m]
    // --- GEMM2 ---
    {
        dim3 grid(CDIM / BN, (MROWS + BM - 1) / BM);
        gemm_out<<<grid, 256, DYN_SMEM>>>(bproj, out);
    }
}

// round 15
// speedup vs baseline: 2.3897x; 1.2504x over previous
#include <cuda_runtime.h>
#include <cuda_fp16.h>
#include <math_constants.h>
#include <cstdint>

// ---------------------------------------------------------------------------
// MiTA Attention. compute_103 PTX target (no tcgen05) -> mma.sync HMMA fp16.
// ALL GEMMs via fp16x3 split folded into K (A=[h,h,l], B=[h,l,h], K'=3K):
// error ~2^-22 (fp16 pair representation limit) — decision-safe AND half the
// work of the previous bf16x6 q/k path. Physical storage [h|l], 2-bit k-block
// remap in the GEMM loader.
// ---------------------------------------------------------------------------

#define BATCH 8
#define NTOK 1025
#define CDIM 1024
#define HEADS 16
#define HDIM 64
#define MEXP 25
#define KSEL 25
#define GRID 32
#define POOLN 5
#define SCALE 0.125f
#define MROWS (BATCH * NTOK)       // 8200
#define BH (BATCH * HEADS)         // 128
#define KL3 (3 * CDIM)             // 3072 logical K'
#define LDP (2 * CDIM)             // 2048 physical ld ([h|l])

// ---------------- scratch ----------------
__device__ float g_qkv[BATCH * NTOK * 3 * CDIM];
__device__ float g_router[BATCH * MEXP * CDIM];
__device__ float g_rlog[BH * MEXP * NTOK];
__device__ float g_gate[BH * MEXP * NTOK];        // layout [bh][m][n]
__device__ int   g_topk[BH * MEXP * KSEL];
__device__ float g_agentv[BH * MEXP * HDIM];
__device__ float g_avpart[4][BH * MEXP * HDIM];
__device__ int   g_cnt[BH * MEXP];
__device__ int   g_qlist[BH * MEXP * NTOK];
__device__ __half g_ax[MROWS * LDP];              // x splits [h|l]  (33.6 MB)
__device__ __half g_aat[MROWS * LDP];             // attn splits [h|l]
__device__ __half g_bqkv[3 * CDIM * LDP];         // Wqkv^T [h|l]   (12.6 MB)
__device__ __half g_bp[CDIM * LDP];               // Wproj^T [h|l]

// k-block maps (2 bits per logical 1024-block): A=[h,h,l], B=[h,l,h]
#define AMAP 0x10u
#define BMAP 0x4u

// ======================= helpers ===========================================
__device__ __forceinline__ uint32_t smem_u32(const void* p) {
    uint32_t a;
    asm("{ .reg .u64 t; cvta.to.shared.u64 t, %1; cvt.u32.u64 %0, t; }" : "=r"(a) : "l"(p));
    return a;
}
#define CP16(dst, src, nbytes) \
    asm volatile("cp.async.cg.shared.global [%0], [%1], 16, %2;" \
        :: "r"(dst), "l"(src), "r"(nbytes) : "memory")

__device__ __forceinline__ void ldmx4(uint32_t& r0, uint32_t& r1, uint32_t& r2,
                                      uint32_t& r3, uint32_t addr) {
    asm volatile("ldmatrix.sync.aligned.m8n8.x4.shared.b16 {%0,%1,%2,%3}, [%4];"
        : "=r"(r0), "=r"(r1), "=r"(r2), "=r"(r3) : "r"(addr));
}
__device__ __forceinline__ void mma16816(float* c, const uint32_t* a,
                                         uint32_t b0, uint32_t b1) {
    asm volatile(
        "mma.sync.aligned.m16n8k16.row.col.f32.f16.f16.f32 "
        "{%0,%1,%2,%3}, {%4,%5,%6,%7}, {%8,%9}, {%0,%1,%2,%3};"
        : "+f"(c[0]), "+f"(c[1]), "+f"(c[2]), "+f"(c[3])
        : "r"(a[0]), "r"(a[1]), "r"(a[2]), "r"(a[3]), "r"(b0), "r"(b1));
}

// ======================= HMMA GEMM body ====================================
#define BM 128
#define BN 128
#define BKE 64
#define STAGES 3
#define TILE_BYTES (128 * 128)
#define SM_A 0
#define SM_B (STAGES * TILE_BYTES)
#define DYN_SMEM (2 * STAGES * TILE_BYTES + 1024)
#define NKT (KL3 / BKE)            // 48 for every GEMM

__device__ __forceinline__ void load_tile(
    const __half* __restrict__ A, const __half* __restrict__ Bt,
    int Mrows, int rowBase, int colBase, int kt, int buf, uint32_t sb, int tid)
{
    const int k0 = kt * BKE;
    const int kblk = k0 >> 10, koff = k0 & 1023;
    const int aoff = (int)((AMAP >> (2 * kblk)) & 3u) * 1024 + koff;
    const int boff = (int)((BMAP >> (2 * kblk)) & 3u) * 1024 + koff;
    #pragma unroll
    for (int j = 0; j < 4; j++) {
        int i = tid + 256 * j;
        int r = i >> 3, c = i & 7;
        uint32_t dst = sb + SM_A + buf * TILE_BYTES
                     + r * 128 + ((c * 16) ^ ((r & 7) * 16));
        bool ok = (rowBase + r) < Mrows;
        const __half* src = ok ? (A + (size_t)(rowBase + r) * LDP + aoff + c * 8) : A;
        CP16(dst, src, ok ? 16 : 0);
    }
    #pragma unroll
    for (int j = 0; j < 4; j++) {
        int i = tid + 256 * j;
        int r = i >> 3, c = i & 7;
        uint32_t dst = sb + SM_B + buf * TILE_BYTES
                     + r * 128 + ((c * 16) ^ ((r & 7) * 16));
        const __half* src = Bt + (size_t)(colBase + r) * LDP + boff + c * 8;
        CP16(dst, src, 16);
    }
    asm volatile("cp.async.commit_group;" ::: "memory");
}

__device__ __forceinline__ void gemm_body(
    const __half* __restrict__ A, const __half* __restrict__ Bt,
    const float* __restrict__ bias, float* __restrict__ C, int ldc,
    int Mrows, int rowBase, int colBase, uint32_t sb, int tid)
{
    const int lane = tid & 31, w = tid >> 5;
    const int wm = w >> 1, wn = w & 1;

    const uint32_t xm = (lane & 7) * 16;
    uint32_t aRow[2];
    #pragma unroll
    for (int mi = 0; mi < 2; mi++)
        aRow[mi] = (uint32_t)(wm * 32 + mi * 16 + (lane & 15)) * 128u;
    const uint32_t aCol = 16u * (lane >> 4);
    uint32_t bRow[4];
    #pragma unroll
    for (int p = 0; p < 4; p++)
        bRow[p] = (uint32_t)(wn * 64 + p * 16 + (lane & 7) + 8 * (lane >> 4)) * 128u;
    const uint32_t bCol = 16u * ((lane >> 3) & 1);

    float acc[2][8][4];
    #pragma unroll
    for (int mi = 0; mi < 2; mi++)
        #pragma unroll
        for (int ni = 0; ni < 8; ni++)
            #pragma unroll
            for (int r = 0; r < 4; r++) acc[mi][ni][r] = 0.f;

    load_tile(A, Bt, Mrows, rowBase, colBase, 0, 0, sb, tid);
    load_tile(A, Bt, Mrows, rowBase, colBase, 1, 1, sb, tid);

    for (int kt = 0; kt < NKT; kt++) {
        if (kt == NKT - 1) asm volatile("cp.async.wait_group 0;" ::: "memory");
        else               asm volatile("cp.async.wait_group 1;" ::: "memory");
        __syncthreads();

        if (kt + 2 < NKT)
            load_tile(A, Bt, Mrows, rowBase, colBase, kt + 2, (kt + 2) % STAGES, sb, tid);

        const int buf = kt % STAGES;
        const uint32_t baseA = sb + SM_A + buf * TILE_BYTES;
        const uint32_t baseB = sb + SM_B + buf * TILE_BYTES;
        #pragma unroll
        for (int kf = 0; kf < 4; kf++) {
            const uint32_t kb = kf * 32;
            uint32_t af[2][4], bf[8][2];
            #pragma unroll
            for (int mi = 0; mi < 2; mi++)
                ldmx4(af[mi][0], af[mi][1], af[mi][2], af[mi][3],
                      baseA + aRow[mi] + ((kb + aCol) ^ xm));
            #pragma unroll
            for (int p = 0; p < 4; p++)
                ldmx4(bf[2 * p][0], bf[2 * p][1], bf[2 * p + 1][0], bf[2 * p + 1][1],
                      baseB + bRow[p] + ((kb + bCol) ^ xm));
            #pragma unroll
            for (int mi = 0; mi < 2; mi++)
                #pragma unroll
                for (int ni = 0; ni < 8; ni++)
                    mma16816(acc[mi][ni], af[mi], bf[ni][0], bf[ni][1]);
        }
    }

    const int colW = colBase + wn * 64 + 2 * (lane & 3);
    #pragma unroll
    for (int mi = 0; mi < 2; mi++) {
        int r0 = rowBase + wm * 32 + mi * 16 + (lane >> 2);
        #pragma unroll
        for (int ni = 0; ni < 8; ni++) {
            int col = colW + ni * 8;
            float bx = 0.f, by = 0.f;
            if (bias) { bx = bias[col]; by = bias[col + 1]; }
            if (r0 < Mrows)
                *(float2*)&C[(size_t)r0 * ldc + col] =
                    make_float2(acc[mi][ni][0] + bx, acc[mi][ni][1] + by);
            if (r0 + 8 < Mrows)
                *(float2*)&C[(size_t)(r0 + 8) * ldc + col] =
                    make_float2(acc[mi][ni][2] + bx, acc[mi][ni][3] + by);
        }
    }
}

// GEMM1: qkv = x @ Wqkv (uniform fp16x3, 24 col tiles)
__global__ __launch_bounds__(256, 2) void gemm_qkv()
{
    extern __shared__ char dsm[];
    uint32_t sb = (smem_u32(dsm) + 1023u) & ~1023u;
    gemm_body(g_ax, g_bqkv, nullptr, g_qkv, 3 * CDIM,
              MROWS, blockIdx.y * BM, blockIdx.x * BN, sb, threadIdx.x);
}

// GEMM2: out = attn @ Wproj + b
__global__ __launch_bounds__(256, 2) void gemm_out(const float* bias, float* C)
{
    extern __shared__ char dsm[];
    uint32_t sb = (smem_u32(dsm) + 1023u) & ~1023u;
    gemm_body(g_aat, g_bp, bias, C, CDIM,
              MROWS, blockIdx.y * BM, blockIdx.x * BN, sb, threadIdx.x);
}

// ======================= split / transpose conversions =====================
// src rows [R][1024] fp32 -> dst [R][2048] = [h|l] fp16
__global__ __launch_bounds__(256) void split_hl(
    const float* __restrict__ src, __half* __restrict__ dst, int total)
{
    int idx = blockIdx.x * 256 + threadIdx.x;
    if (idx >= total) return;
    int r = idx >> 10, k = idx & 1023;
    float v = src[idx];
    __half h = __float2half_rn(v);
    __half l = __float2half_rn(v - __half2float(h));
    size_t o = (size_t)r * LDP + k;
    dst[o] = h;
    dst[o + 1024] = l;
}

// W [1024(k)][Ncols] col slice -> Bt [N][2048] = [h|l] fp16 (transposed)
__global__ __launch_bounds__(256) void transpose_hl(
    const float* __restrict__ W, int ldw, __half* __restrict__ Bt)
{
    __shared__ float t[32][33];
    int n0 = blockIdx.x * 32, k0 = blockIdx.y * 32;
    int tx = threadIdx.x & 31, ty = threadIdx.x >> 5;
    #pragma unroll
    for (int i = 0; i < 32; i += 8)
        t[ty + i][tx] = W[(size_t)(k0 + ty + i) * ldw + n0 + tx];
    __syncthreads();
    #pragma unroll
    for (int i = 0; i < 32; i += 8) {
        int n = n0 + ty + i, k = k0 + tx;
        float v = t[tx][ty + i];
        __half h = __float2half_rn(v);
        __half l = __float2half_rn(v - __half2float(h));
        size_t o = (size_t)n * LDP + k;
        Bt[o] = h;
        Bt[o + 1024] = l;
    }
}

// ======================= small pipeline kernels ============================
__global__ void router_pool_kernel()
{
    int blk = blockIdx.x;
    int b = blk / MEXP, m = blk % MEXP;
    int p = m / POOLN, q = m % POOLN;
    int hs = (p * GRID) / POOLN, he = ((p + 1) * GRID + POOLN - 1) / POOLN;
    int ws = (q * GRID) / POOLN, we = ((q + 1) * GRID + POOLN - 1) / POOLN;
    float inv = 1.0f / (float)((he - hs) * (we - ws));
    for (int c = threadIdx.x; c < CDIM; c += blockDim.x) {
        float s = 0.f;
        for (int h = hs; h < he; h++)
            for (int w = ws; w < we; w++)
                s += g_qkv[((size_t)(b * NTOK + h * GRID + w)) * (3 * CDIM) + c];
        g_router[(size_t)blk * CDIM + c] = s * inv;
    }
}

__global__ __launch_bounds__(256) void zero_cnt()
{
    int idx = blockIdx.x * 256 + threadIdx.x;
    if (idx < BH * MEXP) g_cnt[idx] = 0;
}

// logits + fused per-query expert argmax & bucketing.
#define LT 64
__global__ __launch_bounds__(256) void logits_kernel()
{
    __shared__ float q_s[LT][65];
    __shared__ float k_s[LT][65];
    __shared__ float r_s[MEXP][65];
    __shared__ float gq[LT][28];

    int bh = blockIdx.y;
    int b = bh / HEADS, h = bh % HEADS;
    int n0 = blockIdx.x * LT;
    int tid = threadIdx.x;

    for (int i = tid; i < MEXP * 16; i += 256) {
        int m = i >> 4, c = (i & 15) * 4;
        float4 v = *(const float4*)&g_router[(size_t)(b * MEXP + m) * CDIM + h * HDIM + c];
        r_s[m][c] = v.x; r_s[m][c + 1] = v.y; r_s[m][c + 2] = v.z; r_s[m][c + 3] = v.w;
    }
    #pragma unroll
    for (int it = 0; it < 4; it++) {
        int i = tid + it * 256;
        int row = i >> 4, c = (i & 15) * 4;
        int n = n0 + row;
        float4 qv = make_float4(0.f, 0.f, 0.f, 0.f), kv = qv;
        if (n < NTOK) {
            const float* base = &g_qkv[(size_t)(b * NTOK + n) * (3 * CDIM) + h * HDIM + c];
            qv = *(const float4*)base;
            kv = *(const float4*)(base + CDIM);
        }
        q_s[row][c] = qv.x; q_s[row][c + 1] = qv.y; q_s[row][c + 2] = qv.z; q_s[row][c + 3] = qv.w;
        k_s[row][c] = kv.x; k_s[row][c + 1] = kv.y; k_s[row][c + 2] = kv.z; k_s[row][c + 3] = kv.w;
    }
    __syncthreads();

    const int nl = tid & 63;
    const int g = tid >> 6;
    float acck[7], accq[7];
    #pragma unroll
    for (int j = 0; j < 7; j++) { acck[j] = 0.f; accq[j] = 0.f; }

    for (int d = 0; d < HDIM; d++) {
        float qv = q_s[nl][d];
        float kv = k_s[nl][d];
        #pragma unroll
        for (int j = 0; j < 7; j++) {
            int m = g + 4 * j;
            int mc = (m < MEXP) ? m : 0;
            float r = r_s[mc][d];
            acck[j] += r * kv;
            accq[j] += r * qv;
        }
    }
    int n = n0 + nl;
    if (n < NTOK) {
        #pragma unroll
        for (int j = 0; j < 7; j++) {
            int m = g + 4 * j;
            if (m < MEXP) {
                size_t o = ((size_t)(bh * MEXP + m)) * NTOK + n;
                g_rlog[o] = acck[j];
                g_gate[o] = accq[j];
                gq[nl][m] = accq[j];
            }
        }
    }
    __syncthreads();

    if (tid < LT) {
        int n2 = n0 + tid;
        if (n2 < NTOK) {
            float best = -CUDART_INF_F; int ei = 0;
            #pragma unroll
            for (int m = 0; m < MEXP; m++) {
                float v = gq[tid][m];
                if (v > best) { best = v; ei = m; }
            }
            int blk = bh * MEXP + ei;
            int pos = atomicAdd(&g_cnt[blk], 1);
            g_qlist[(size_t)blk * NTOK + pos] = n2;
        }
    }
}

__global__ __launch_bounds__(256) void softmax_topk_kernel()
{
    __shared__ float swv[8];
    __shared__ int   swi[8];
    __shared__ float selv[KSEL];
    __shared__ int   seli[KSEL];
    __shared__ float s_inv;

    int row = blockIdx.x;
    float* r = &g_rlog[(size_t)row * NTOK];
    int tid = threadIdx.x, lane = tid & 31, wid = tid >> 5;

    float vals[5];
    #pragma unroll
    for (int i = 0; i < 5; i++) {
        int n = tid + (i << 8);
        vals[i] = (n < NTOK) ? r[n] : -CUDART_INF_F;
    }

    for (int it = 0; it < KSEL; it++) {
        float bv = -CUDART_INF_F; int bi = 0x7FFFFFFF;
        #pragma unroll
        for (int i = 0; i < 5; i++) {
            int n = tid + (i << 8);
            float v = vals[i];
            if (v > bv || (v == bv && n < bi)) { bv = v; bi = n; }
        }
        #pragma unroll
        for (int off = 16; off > 0; off >>= 1) {
            float ov = __shfl_xor_sync(0xFFFFFFFFu, bv, off);
            int   oi = __shfl_xor_sync(0xFFFFFFFFu, bi, off);
            if (ov > bv || (ov == bv && oi < bi)) { bv = ov; bi = oi; }
        }
        if (lane == 0) { swv[wid] = bv; swi[wid] = bi; }
        __syncthreads();
        if (tid == 0) {
            float gv = swv[0]; int gi = swi[0];
            #pragma unroll
            for (int ww = 1; ww < 8; ww++)
                if (swv[ww] > gv || (swv[ww] == gv && swi[ww] < gi)) { gv = swv[ww]; gi = swi[ww]; }
            selv[it] = gv; seli[it] = gi;
        }
        __syncthreads();
        int sn = seli[it];
        if (tid == (sn & 255)) vals[sn >> 8] = -CUDART_INF_F;
    }

    if (tid < KSEL) g_topk[(size_t)row * KSEL + tid] = seli[tid];
    float mx = selv[0];
    for (int it = 0; it < KSEL; it++) {
        int sn = seli[it];
        if (tid == (sn & 255)) vals[sn >> 8] = selv[it];
    }

    float ev[5];
    float psum = 0.f;
    #pragma unroll
    for (int i = 0; i < 5; i++) {
        int n = tid + (i << 8);
        float e = (n < NTOK) ? __expf((vals[i] - mx) * SCALE) : 0.f;
        ev[i] = e;
        psum += e;
    }
    #pragma unroll
    for (int off = 16; off > 0; off >>= 1)
        psum += __shfl_xor_sync(0xFFFFFFFFu, psum, off);
    if (lane == 0) swv[wid] = psum;
    __syncthreads();
    if (tid == 0) {
        float s = 0.f;
        #pragma unroll
        for (int ww = 0; ww < 8; ww++) s += swv[ww];
        s_inv = 1.0f / s;
    }
    __syncthreads();
    float inv = s_inv;
    #pragma unroll
    for (int i = 0; i < 5; i++) {
        int n = tid + (i << 8);
        if (n < NTOK) r[n] = ev[i] * inv;
    }
}

#define AV_TILES 33
__global__ __launch_bounds__(256) void agent_value_part()
{
    __shared__ float p_s[MEXP][32];
    __shared__ float v_s[32][HDIM];
    int bh = blockIdx.x;
    int ch = blockIdx.y;
    int b = bh / HEADS, h = bh % HEADS;
    int tid = threadIdx.x;
    int tile0 = ch * 9;
    int tile1 = tile0 + 9; if (tile1 > AV_TILES) tile1 = AV_TILES;

    float acc[7];
    #pragma unroll
    for (int i = 0; i < 7; i++) acc[i] = 0.f;

    for (int tile = tile0; tile < tile1; tile++) {
        int t0 = tile * 32;
        for (int e = tid; e < MEXP * 32; e += 256) {
            int m = e / 32, n = e % 32;
            p_s[m][n] = (t0 + n < NTOK)
                ? g_rlog[((size_t)(bh * MEXP + m)) * NTOK + t0 + n] : 0.f;
        }
        for (int e = tid; e < 32 * HDIM; e += 256) {
            int n = e / HDIM, d = e % HDIM;
            v_s[n][d] = (t0 + n < NTOK)
                ? g_qkv[(size_t)(b * NTOK + t0 + n) * (3 * CDIM) + 2 * CDIM + h * HDIM + d]
                : 0.f;
        }
        __syncthreads();
        for (int n = 0; n < 32; n++) {
            #pragma unroll
            for (int i = 0; i < 7; i++) {
                int pidx = tid + 256 * i;
                if (pidx < MEXP * HDIM) {
                    int m = pidx >> 6, d = pidx & 63;
                    acc[i] += p_s[m][n] * v_s[n][d];
                }
            }
        }
        __syncthreads();
    }
    #pragma unroll
    for (int i = 0; i < 7; i++) {
        int pidx = tid + 256 * i;
        if (pidx < MEXP * HDIM)
            g_avpart[ch][(size_t)bh * MEXP * HDIM + pidx] = acc[i];
    }
}

__global__ __launch_bounds__(256) void agent_value_reduce()
{
    int idx = blockIdx.x * 256 + threadIdx.x;
    if (idx < BH * MEXP * HDIM)
        g_agentv[idx] = g_avpart[0][idx] + g_avpart[1][idx]
                      + g_avpart[2][idx] + g_avpart[3][idx];
}

// ======================= expert-grouped attention ==========================
__global__ __launch_bounds__(256) void attn_expert()
{
    __shared__ float K_s[HDIM][KSEL + 1];
    __shared__ float V_s[KSEL][HDIM];
    __shared__ float ag_s[MEXP][HDIM];
    __shared__ int   keys[KSEL];
    __shared__ float q_s[8][HDIM];
    __shared__ float w_s[8][2 * KSEL];

    int blk = blockIdx.x;
    int nq = g_cnt[blk];
    if (nq == 0) return;

    int bh = blk / MEXP;
    int b = bh / HEADS, h = bh % HEADS;
    int tid = threadIdx.x;
    int warp = tid >> 5, lane = tid & 31;

    if (tid < KSEL) keys[tid] = g_topk[(size_t)blk * KSEL + tid];
    __syncthreads();

    for (int e = tid; e < KSEL * HDIM; e += 256) {
        int k = e >> 6, d = e & 63;
        const float* base = &g_qkv[(size_t)(b * NTOK + keys[k]) * (3 * CDIM) + h * HDIM + d];
        K_s[d][k] = base[CDIM];
        V_s[k][d] = base[2 * CDIM];
    }
    for (int e = tid; e < MEXP * HDIM; e += 256)
        ((float*)ag_s)[e] = g_agentv[(size_t)bh * MEXP * HDIM + e];
    __syncthreads();

    const int* ql = &g_qlist[(size_t)blk * NTOK];
    for (int iq = warp; iq < nq; iq += 8) {
        int n = ql[iq];
        float2 qp = *(const float2*)
            &g_qkv[(size_t)(b * NTOK + n) * (3 * CDIM) + h * HDIM + 2 * lane];
        q_s[warp][2 * lane] = qp.x;
        q_s[warp][2 * lane + 1] = qp.y;
        __syncwarp();

        float gv = -CUDART_INF_F, mv = -CUDART_INF_F;
        if (lane < KSEL) {
            gv = g_gate[((size_t)bh * MEXP + lane) * NTOK + n] * SCALE;
            float acc = 0.f;
            #pragma unroll
            for (int d = 0; d < HDIM; d++)
                acc += q_s[warp][d] * K_s[d][lane];
            mv = acc * SCALE;
        }
        float mx = fmaxf(gv, mv);
        #pragma unroll
        for (int off = 16; off > 0; off >>= 1)
            mx = fmaxf(mx, __shfl_xor_sync(0xFFFFFFFFu, mx, off));
        float eg = (lane < KSEL) ? __expf(gv - mx) : 0.f;
        float em = (lane < KSEL) ? __expf(mv - mx) : 0.f;
        float s = eg + em;
        #pragma unroll
        for (int off = 16; off > 0; off >>= 1)
            s += __shfl_xor_sync(0xFFFFFFFFu, s, off);
        float inv = 1.0f / s;
        if (lane < KSEL) {
            w_s[warp][lane] = eg * inv;
            w_s[warp][KSEL + lane] = em * inv;
        }
        __syncwarp();

        float o0 = 0.f, o1 = 0.f;
        #pragma unroll
        for (int j = 0; j < KSEL; j++) {
            float wa = w_s[warp][j];
            float wm = w_s[warp][KSEL + j];
            float2 av = *(const float2*)&ag_s[j][2 * lane];
            float2 vv = *(const float2*)&V_s[j][2 * lane];
            o0 += wa * av.x + wm * vv.x;
            o1 += wa * av.y + wm * vv.y;
        }
        // write [h|l] fp16 (GEMM2 maps [h,h,l])
        __half h0 = __float2half_rn(o0);
        __half l0 = __float2half_rn(o0 - __half2float(h0));
        __half h1 = __float2half_rn(o1);
        __half l1 = __float2half_rn(o1 - __half2float(h1));
        size_t oo = (size_t)(b * NTOK + n) * LDP + h * HDIM + 2 * lane;
        __half2 ph; ph.x = h0; ph.y = h1;
        __half2 pl; pl.x = l0; pl.y = l1;
        *(__half2*)&g_aat[oo] = ph;
        *(__half2*)&g_aat[oo + 1024] = pl;
        __syncwarp();
    }
}

// ---------------------------------------------------------------------------
extern "C" void kernel_launch(void* const* d_in, const int* in_sizes, int n_in,
                              void* d_out, int out_size)
{
    const float* x     = (const float*)d_in[0];
    const float* Wqkv  = (const float*)d_in[1];
    const float* Wproj = (const float*)d_in[2];
    const float* bproj = (const float*)d_in[3];
    float* out = (float*)d_out;

    __half* ax;   cudaGetSymbolAddress((void**)&ax,   g_ax);
    __half* bqkv; cudaGetSymbolAddress((void**)&bqkv, g_bqkv);
    __half* bp;   cudaGetSymbolAddress((void**)&bp,   g_bp);

    cudaFuncSetAttribute(gemm_qkv, cudaFuncAttributeMaxDynamicSharedMemorySize, DYN_SMEM);
    cudaFuncSetAttribute(gemm_out, cudaFuncAttributeMaxDynamicSharedMemorySize, DYN_SMEM);

    // --- conversions ---
    split_hl<<<(MROWS * CDIM + 255) / 256, 256>>>(x, ax, MROWS * CDIM);
    {
        dim3 g(3 * CDIM / 32, CDIM / 32);                // (96, 32)
        transpose_hl<<<g, 256>>>(Wqkv, 3 * CDIM, bqkv);
    }
    {
        dim3 g(CDIM / 32, CDIM / 32);
        transpose_hl<<<g, 256>>>(Wproj, CDIM, bp);
    }
    // --- GEMM1: qkv = x @ Wqkv (fp16x3) ---
    {
        dim3 grid(3 * CDIM / BN, (MROWS + BM - 1) / BM); // (24, 65)
        gemm_qkv<<<grid, 256, DYN_SMEM>>>();
    }
    router_pool_kernel<<<BATCH * MEXP, 256>>>();
    zero_cnt<<<(BH * MEXP + 255) / 256, 256>>>();
    {
        dim3 grid((NTOK + LT - 1) / LT, BH);
        logits_kernel<<<grid, 256>>>();                  // + expert bucketing
    }
    softmax_topk_kernel<<<BH * MEXP, 256>>>();
    {
        dim3 grid(BH, 4);
        agent_value_part<<<grid, 256>>>();
    }
    agent_value_reduce<<<(BH * MEXP * HDIM + 255) / 256, 256>>>();
    attn_expert<<<BH * MEXP, 256>>>();                   // writes g_aat [h|l]
    // --- GEMM2: out = attn @ Wproj + b (fp16x3) ---
    {
        dim3 grid(CDIM / BN, (MROWS + BM - 1) / BM);     // (8, 65)
        gemm_out<<<grid, 256, DYN_SMEM>>>(bproj, out);
    }
}